// round 7
// baseline (speedup 1.0000x reference)
#include <cuda_runtime.h>
#include <cuda_bf16.h>
#include <math.h>
#include <stdint.h>

#define D 1024
#define EXP 7
#define NTOK 8192
#define CAP 2574            // int(8192*2/7*1.1)
#define NSLOTS (EXP*CAP)    // 18018

// ======================= device scratch (no runtime allocation) =======================
// Referenced ONLY from device code (host-side symbol addresses of __device__ vars are invalid).
__device__ alignas(16) __nv_bfloat16 g_x_hi[NTOK * D],  g_x_lo[NTOK * D];
__device__ alignas(16) __nv_bfloat16 g_Hs_hi[NTOK * D], g_Hs_lo[NTOK * D];
__device__ alignas(16) __nv_bfloat16 g_He_hi[NSLOTS * D], g_He_lo[NSLOTS * D];
__device__ alignas(16) __nv_bfloat16 g_W1t_hi[EXP * D * D], g_W1t_lo[EXP * D * D];
__device__ alignas(16) __nv_bfloat16 g_W2t_hi[EXP * D * D], g_W2t_lo[EXP * D * D];
__device__ alignas(16) __nv_bfloat16 g_Ws1t_hi[D * D], g_Ws1t_lo[D * D];
__device__ alignas(16) __nv_bfloat16 g_Ws2t_hi[D * D], g_Ws2t_lo[D * D];
__device__ alignas(16) float g_Oexp[NSLOTS * D];
__device__ int   g_slot_token[NSLOTS];
__device__ int   g_slot_of[NTOK * 2];
__device__ int   g_top[NTOK];
__device__ float g_gate0[NTOK];
__device__ float g_gate1[NTOK];
__device__ int   g_mask[NTOK];

// ======================= helpers (base ISA only: sm_80+) =======================
__device__ __forceinline__ uint32_t smem_to_u32(const void* p) {
    uint32_t a;
    asm("{ .reg .u64 t; cvta.to.shared.u64 t, %1; cvt.u32.u64 %0, t; }" : "=r"(a) : "l"(p));
    return a;
}
__device__ __forceinline__ void ldsm4(uint32_t& r0, uint32_t& r1, uint32_t& r2, uint32_t& r3,
                                      uint32_t addr) {
    asm volatile("ldmatrix.sync.aligned.m8n8.x4.shared.b16 {%0,%1,%2,%3}, [%4];"
                 : "=r"(r0), "=r"(r1), "=r"(r2), "=r"(r3) : "r"(addr));
}
__device__ __forceinline__ void mma16816(float* d, const uint32_t* a, const uint32_t* b) {
    asm volatile(
        "mma.sync.aligned.m16n8k16.row.col.f32.bf16.bf16.f32 "
        "{%0,%1,%2,%3}, {%4,%5,%6,%7}, {%8,%9}, {%0,%1,%2,%3};"
        : "+f"(d[0]), "+f"(d[1]), "+f"(d[2]), "+f"(d[3])
        : "r"(a[0]), "r"(a[1]), "r"(a[2]), "r"(a[3]), "r"(b[0]), "r"(b[1]));
}
__device__ __forceinline__ void cp_async16(uint32_t dst, const void* src, int src_size) {
    asm volatile("cp.async.cg.shared.global [%0], [%1], 16, %2;"
                 :: "r"(dst), "l"(src), "r"(src_size) : "memory");
}
#define CP_COMMIT() asm volatile("cp.async.commit_group;" ::: "memory")
#define CP_WAIT1()  asm volatile("cp.async.wait_group 1;" ::: "memory")

// ======================= router =======================
__global__ void __launch_bounds__(256) router_kernel(
    const float* __restrict__ x, const float* __restrict__ noise,
    const float* __restrict__ Wr, const float* __restrict__ br,
    const float* __restrict__ Wn, const float* __restrict__ bn)
{
    int n = blockIdx.x;
    const float* xr = x + (size_t)n * D;
    float aR[EXP], aN[EXP];
#pragma unroll
    for (int e = 0; e < EXP; e++) { aR[e] = 0.f; aN[e] = 0.f; }
    for (int d = threadIdx.x; d < D; d += 256) {
        float xv = xr[d];
        const float* wr = Wr + d * EXP;
        const float* wn = Wn + d * EXP;
#pragma unroll
        for (int e = 0; e < EXP; e++) {
            aR[e] = fmaf(xv, wr[e], aR[e]);
            aN[e] = fmaf(xv, wn[e], aN[e]);
        }
    }
    __shared__ float wred[8][14];
    int lane = threadIdx.x & 31, warp = threadIdx.x >> 5;
#pragma unroll
    for (int i = 0; i < 14; i++) {
        float v = (i < EXP) ? aR[i] : aN[i - EXP];
#pragma unroll
        for (int o = 16; o > 0; o >>= 1) v += __shfl_down_sync(0xffffffffu, v, o);
        if (lane == 0) wred[warp][i] = v;
    }
    __syncthreads();
    if (threadIdx.x == 0) {
        float logit[EXP];
#pragma unroll
        for (int e = 0; e < EXP; e++) {
            float sR = 0.f, sN = 0.f;
#pragma unroll
            for (int w = 0; w < 8; w++) { sR += wred[w][e]; sN += wred[w][e + EXP]; }
            float z  = sN + bn[e];
            float sp = (z > 20.f) ? z : log1pf(expf(z));
            logit[e] = sR + br[e] + noise[(size_t)n * EXP + e] * sp;
        }
        int e0 = 0; float v0 = logit[0];
#pragma unroll
        for (int e = 1; e < EXP; e++) if (logit[e] > v0) { v0 = logit[e]; e0 = e; }
        int e1 = -1; float v1 = -INFINITY;
#pragma unroll
        for (int e = 0; e < EXP; e++) if (e != e0 && logit[e] > v1) { v1 = logit[e]; e1 = e; }
        float ex = expf(v1 - v0);
        g_top[n]   = e0 | (e1 << 4);
        g_gate0[n] = 1.f / (1.f + ex);
        g_gate1[n] = ex / (1.f + ex);
        g_mask[n]  = (1 << e0) | (1 << e1);
        g_slot_of[2 * n]     = -1;
        g_slot_of[2 * n + 1] = -1;
    }
}

// ======================= slot init =======================
__global__ void init_slots()
{
    int i = blockIdx.x * 256 + threadIdx.x;
    if (i < NSLOTS) g_slot_token[i] = 1 << 30;
}

// ======================= ordered capacity scan (single block) =======================
__global__ void __launch_bounds__(1024) scan_kernel(float* __restrict__ dout, int lbl_idx)
{
    __shared__ int   base[EXP];
    __shared__ float probsum[EXP];
    __shared__ int   cnt[EXP];
    __shared__ int   wcnt[32];
    __shared__ int   woff[32];
    __shared__ int   total_s;
    int tid = threadIdx.x, lane = tid & 31, warp = tid >> 5;
    if (tid < EXP) { base[tid] = 0; probsum[tid] = 0.f; cnt[tid] = 0; }
    __syncthreads();

    for (int tile = 0; tile < NTOK / 1024; tile++) {
        int n  = tile * 1024 + tid;
        int mk = g_mask[n];
        int tp = g_top[n];
        int e0 = tp & 15, e1 = (tp >> 4) & 15;
        atomicAdd(&probsum[e0], g_gate0[n]);
        atomicAdd(&probsum[e1], g_gate1[n]);
        atomicAdd(&cnt[e0], 1);
        atomicAdd(&cnt[e1], 1);
#pragma unroll
        for (int e = 0; e < EXP; e++) {
            int flag = (mk >> e) & 1;
            unsigned bal = __ballot_sync(0xffffffffu, flag != 0);
            if (lane == 0) wcnt[warp] = __popc(bal);
            __syncthreads();
            if (warp == 0) {
                int v = wcnt[lane];
                int inc = v;
#pragma unroll
                for (int o = 1; o < 32; o <<= 1) {
                    int t = __shfl_up_sync(0xffffffffu, inc, o);
                    if (lane >= o) inc += t;
                }
                woff[lane] = inc - v;
                if (lane == 31) total_s = inc;
            }
            __syncthreads();
            if (flag) {
                int pos = base[e] + woff[warp] + __popc(bal & ((1u << lane) - 1u));
                if (pos < CAP) {
                    int slot = e * CAP + pos;
                    g_slot_token[slot] = n;
                    int k = (e == e0) ? 0 : 1;
                    g_slot_of[2 * n + k] = slot;
                }
            }
            __syncthreads();
            if (tid == 0) base[e] += total_s;
            __syncthreads();
        }
    }
    if (tid == 0) {
        float s = 0.f;
#pragma unroll
        for (int e = 0; e < EXP; e++)
            s += (probsum[e] / (float)NTOK) * ((float)cnt[e] / (float)NTOK);
        dout[lbl_idx] = (float)EXP * s;
    }
}

// ======================= split / transpose prep =======================
__global__ void __launch_bounds__(256) split_x_kernel(const float* __restrict__ x)
{
    int i = blockIdx.x * 256 + threadIdx.x;
    if (i < NTOK * D) {
        float v = x[i];
        __nv_bfloat16 h = __float2bfloat16(v);
        g_x_hi[i] = h;
        g_x_lo[i] = __float2bfloat16(v - __bfloat162float(h));
    }
}

// W[m][k][n] fp32 -> Wt[m][n][k] bf16 hi/lo. Destination selected by template (device symbols).
template <int WSEL>
__global__ void __launch_bounds__(256) wsplit_kernel(const float* __restrict__ W)
{
    __nv_bfloat16* hi; __nv_bfloat16* lo;
    if constexpr (WSEL == 0) { hi = g_Ws1t_hi; lo = g_Ws1t_lo; }
    if constexpr (WSEL == 1) { hi = g_Ws2t_hi; lo = g_Ws2t_lo; }
    if constexpr (WSEL == 2) { hi = g_W1t_hi;  lo = g_W1t_lo;  }
    if constexpr (WSEL == 3) { hi = g_W2t_hi;  lo = g_W2t_lo;  }
    __shared__ float t[32][33];
    int m = blockIdx.z;
    const float* Wm = W + (size_t)m * D * D;
    int n0 = blockIdx.x * 32, k0 = blockIdx.y * 32;
    int tx = threadIdx.x, ty = threadIdx.y;
#pragma unroll
    for (int r = 0; r < 4; r++) {
        int k = k0 + ty + r * 8;
        t[ty + r * 8][tx] = Wm[(size_t)k * D + n0 + tx];
    }
    __syncthreads();
#pragma unroll
    for (int r = 0; r < 4; r++) {
        int n = n0 + ty + r * 8;
        int k = k0 + tx;
        float v = t[tx][ty + r * 8];
        __nv_bfloat16 h = __float2bfloat16(v);
        size_t o = (size_t)m * D * D + (size_t)n * D + k;
        hi[o] = h;
        lo[o] = __float2bfloat16(v - __bfloat162float(h));
    }
}

// ======================= HMMA bf16x2-split GEMM =======================
// Block 256x128 (M x N), K' = 3*1024 in 48 chunks of 64. cp.async double buffer.
// 256 threads; warp grid 2(M) x 4(N); warp tile 128x32; mma.m16n8k16.
// MODE 0: shared FFN1  A=x(split)        B=Ws1t  relu -> Hs(split)
// MODE 1: shared FFN2  A=Hs(split)       B=Ws2t       -> OutF param (d_out)
// MODE 2: expert FFN1  A=gather x(split) B=W1t[z] relu-> He(split)   grid.z=EXP
// MODE 3: expert FFN2  A=He(split)       B=W2t[z]     -> g_Oexp      grid.z=EXP
#define NCHUNK 48
#define BM 256
#define A_STAGE 32768                 // 256 rows x 128B
#define B_STAGE 16384                 // 128 rows x 128B
#define STAGE_BYTES (A_STAGE + B_STAGE)
#define GEMM_SMEM (2 * STAGE_BYTES + 1024)

template <int MODE>
__global__ void __launch_bounds__(256) moe_gemm(
    const float* __restrict__ bias, float* __restrict__ OutF, int M)
{
    constexpr bool GATHER = (MODE == 2);
    constexpr bool RELU   = (MODE == 0 || MODE == 2);
    extern __shared__ char smem[];
    uint32_t smem_base = smem_to_u32(smem);
    int tid = threadIdx.x, wid = tid >> 5, lane = tid & 31;
    int colTile = blockIdx.x, rowTile = blockIdx.y, z = blockIdx.z;
    int wm = wid & 1, wn = wid >> 1;          // 2 x 4 warp grid; warp tile 128x32

    const __nv_bfloat16 *Ahi, *Alo, *Bhi, *Blo;
    __nv_bfloat16 *OutHi = nullptr, *OutLo = nullptr;
    if constexpr (MODE == 0) {
        Ahi = g_x_hi;  Alo = g_x_lo;  Bhi = g_Ws1t_hi; Blo = g_Ws1t_lo;
        OutHi = g_Hs_hi; OutLo = g_Hs_lo;
    }
    if constexpr (MODE == 1) {
        Ahi = g_Hs_hi; Alo = g_Hs_lo; Bhi = g_Ws2t_hi; Blo = g_Ws2t_lo;
    }
    if constexpr (MODE == 2) {
        Ahi = g_x_hi;  Alo = g_x_lo;
        Bhi = g_W1t_hi + (size_t)z * D * D; Blo = g_W1t_lo + (size_t)z * D * D;
        bias += (size_t)z * D;
        OutHi = g_He_hi + (size_t)z * CAP * D; OutLo = g_He_lo + (size_t)z * CAP * D;
    }
    if constexpr (MODE == 3) {
        Ahi = g_He_hi + (size_t)z * CAP * D; Alo = g_He_lo + (size_t)z * CAP * D;
        Bhi = g_W2t_hi + (size_t)z * D * D;  Blo = g_W2t_lo + (size_t)z * D * D;
        bias += (size_t)z * D;
        OutF = g_Oexp + (size_t)z * CAP * D;
    }

    int* s_rowsrc = (int*)(smem + 2 * STAGE_BYTES);
    {
        int gr = rowTile * BM + tid;      // 256 threads cover 256 rows
        int src;
        if constexpr (GATHER) {
            int t = (gr < M) ? g_slot_token[z * CAP + gr] : (1 << 30);
            src = ((unsigned)t < (unsigned)NTOK) ? t : -1;
        } else {
            src = (gr < M) ? gr : -1;
        }
        s_rowsrc[tid] = src;
    }
    __syncthreads();

    // ---- stage loader: chunk c into buffer buf ----
    auto load_stage = [&](int c, int buf) {
        int seg = c >> 4;                       // 0: hiA*hiB  1: loA*hiB  2: hiA*loB
        int kb  = (c & 15) * 64;
        const __nv_bfloat16* aseg = (seg == 1) ? Alo : Ahi;
        const __nv_bfloat16* bseg = (seg == 2) ? Blo : Bhi;
        uint32_t abase = smem_base + buf * STAGE_BYTES;
        uint32_t bbase = abase + A_STAGE;
#pragma unroll
        for (int i = 0; i < 8; i++) {           // A: 256 rows x 8 chunks of 16B
            int chunk = i * 256 + tid;
            int row = chunk >> 3, c0 = chunk & 7;
            uint32_t swc = (uint32_t)(c0 ^ (row & 7));
            int src = s_rowsrc[row];
            const void* ap = aseg + (size_t)(src < 0 ? 0 : src) * D + kb + c0 * 8;
            cp_async16(abase + row * 128 + swc * 16, ap, src < 0 ? 0 : 16);
        }
#pragma unroll
        for (int i = 0; i < 4; i++) {           // B: 128 rows x 8 chunks of 16B
            int chunk = i * 256 + tid;
            int row = chunk >> 3, c0 = chunk & 7;
            uint32_t swc = (uint32_t)(c0 ^ (row & 7));
            int n = colTile * 128 + row;
            cp_async16(bbase + row * 128 + swc * 16,
                       bseg + (size_t)n * D + kb + c0 * 8, 16);
        }
    };

    float acc[8][4][4];
#pragma unroll
    for (int mi = 0; mi < 8; mi++)
#pragma unroll
        for (int ni = 0; ni < 4; ni++)
#pragma unroll
            for (int q = 0; q < 4; q++) acc[mi][ni][q] = 0.f;

    load_stage(0, 0); CP_COMMIT();
    load_stage(1, 1); CP_COMMIT();

    for (int c = 0; c < NCHUNK; c++) {
        int buf = c & 1;
        CP_WAIT1();
        __syncthreads();
        uint32_t abase = smem_base + buf * STAGE_BYTES;
        uint32_t bbase = abase + A_STAGE;
#pragma unroll
        for (int s = 0; s < 4; s++) {
            uint32_t bfr[4][2];
#pragma unroll
            for (int nb = 0; nb < 2; nb++) {
                int row = wn * 32 + nb * 16 + ((lane >> 4) & 1) * 8 + (lane & 7);
                int kc  = s * 2 + ((lane >> 3) & 1);
                uint32_t addr = bbase + row * 128 + (uint32_t)((kc ^ (row & 7)) << 4);
                uint32_t q0, q1, q2, q3;
                ldsm4(q0, q1, q2, q3, addr);
                bfr[nb * 2][0] = q0;  bfr[nb * 2][1] = q1;
                bfr[nb * 2 + 1][0] = q2; bfr[nb * 2 + 1][1] = q3;
            }
#pragma unroll
            for (int mi = 0; mi < 8; mi++) {
                uint32_t afr[4];
                int row = wm * 128 + mi * 16 + (lane & 15);
                int kc  = s * 2 + (lane >> 4);
                uint32_t addr = abase + row * 128 + (uint32_t)((kc ^ (row & 7)) << 4);
                ldsm4(afr[0], afr[1], afr[2], afr[3], addr);
#pragma unroll
                for (int ni = 0; ni < 4; ni++)
                    mma16816(acc[mi][ni], afr, bfr[ni]);
            }
        }
        __syncthreads();
        if (c + 2 < NCHUNK) load_stage(c + 2, buf);
        CP_COMMIT();
    }

    // ---- epilogue ----
    int rbase = rowTile * BM + wm * 128 + (lane >> 2);
    int cbase = colTile * 128 + wn * 32 + (lane & 3) * 2;
#pragma unroll
    for (int mi = 0; mi < 8; mi++) {
#pragma unroll
        for (int ni = 0; ni < 4; ni++) {
            int cc = cbase + ni * 8;
            float b0 = bias[cc], b1 = bias[cc + 1];
            float v00 = acc[mi][ni][0] + b0, v01 = acc[mi][ni][1] + b1;
            float v10 = acc[mi][ni][2] + b0, v11 = acc[mi][ni][3] + b1;
            int r0 = rbase + mi * 16, r1 = r0 + 8;
            if constexpr (RELU) {
                v00 = fmaxf(v00, 0.f); v01 = fmaxf(v01, 0.f);
                v10 = fmaxf(v10, 0.f); v11 = fmaxf(v11, 0.f);
                if (r0 < M) {
                    __nv_bfloat162 h = __floats2bfloat162_rn(v00, v01);
                    __nv_bfloat162 l = __floats2bfloat162_rn(
                        v00 - __bfloat162float(__low2bfloat16(h)),
                        v01 - __bfloat162float(__high2bfloat16(h)));
                    *(__nv_bfloat162*)(OutHi + (size_t)r0 * D + cc) = h;
                    *(__nv_bfloat162*)(OutLo + (size_t)r0 * D + cc) = l;
                }
                if (r1 < M) {
                    __nv_bfloat162 h = __floats2bfloat162_rn(v10, v11);
                    __nv_bfloat162 l = __floats2bfloat162_rn(
                        v10 - __bfloat162float(__low2bfloat16(h)),
                        v11 - __bfloat162float(__high2bfloat16(h)));
                    *(__nv_bfloat162*)(OutHi + (size_t)r1 * D + cc) = h;
                    *(__nv_bfloat162*)(OutLo + (size_t)r1 * D + cc) = l;
                }
            } else {
                if (r0 < M) *(float2*)(OutF + (size_t)r0 * D + cc) = make_float2(v00, v01);
                if (r1 < M) *(float2*)(OutF + (size_t)r1 * D + cc) = make_float2(v10, v11);
            }
        }
    }
}

// ======================= combine =======================
__global__ void __launch_bounds__(256) combine_kernel(float* __restrict__ out)
{
    int n = blockIdx.x;
    int s0 = g_slot_of[2 * n], s1 = g_slot_of[2 * n + 1];
    float g0 = g_gate0[n], g1 = g_gate1[n];
    float4* orow = (float4*)(out + (size_t)n * D);
    float4 v = orow[threadIdx.x];
    if (s0 >= 0) {
        float4 e = ((const float4*)(g_Oexp + (size_t)s0 * D))[threadIdx.x];
        v.x += g0 * e.x; v.y += g0 * e.y; v.z += g0 * e.z; v.w += g0 * e.w;
    }
    if (s1 >= 0) {
        float4 e = ((const float4*)(g_Oexp + (size_t)s1 * D))[threadIdx.x];
        v.x += g1 * e.x; v.y += g1 * e.y; v.z += g1 * e.z; v.w += g1 * e.w;
    }
    orow[threadIdx.x] = v;
}

// ======================= launch =======================
extern "C" void kernel_launch(void* const* d_in, const int* in_sizes, int n_in,
                              void* d_out, int out_size)
{
    const float* x     = (const float*)d_in[0];
    const float* noise = (const float*)d_in[1];
    const float* Wr    = (const float*)d_in[2];
    const float* br    = (const float*)d_in[3];
    const float* Wn    = (const float*)d_in[4];
    const float* bn    = (const float*)d_in[5];
    const float* W1    = (const float*)d_in[6];
    const float* b1    = (const float*)d_in[7];
    const float* W2    = (const float*)d_in[8];
    const float* b2    = (const float*)d_in[9];
    const float* Ws1   = (const float*)d_in[10];
    const float* bs1   = (const float*)d_in[11];
    const float* Ws2   = (const float*)d_in[12];
    const float* bs2   = (const float*)d_in[13];
    float* out = (float*)d_out;

    cudaFuncSetAttribute(moe_gemm<0>, cudaFuncAttributeMaxDynamicSharedMemorySize, GEMM_SMEM);
    cudaFuncSetAttribute(moe_gemm<1>, cudaFuncAttributeMaxDynamicSharedMemorySize, GEMM_SMEM);
    cudaFuncSetAttribute(moe_gemm<2>, cudaFuncAttributeMaxDynamicSharedMemorySize, GEMM_SMEM);
    cudaFuncSetAttribute(moe_gemm<3>, cudaFuncAttributeMaxDynamicSharedMemorySize, GEMM_SMEM);

    router_kernel<<<NTOK, 256>>>(x, noise, Wr, br, Wn, bn);
    init_slots<<<(NSLOTS + 255) / 256, 256>>>();
    scan_kernel<<<1, 1024>>>(out, out_size - 1);

    split_x_kernel<<<(NTOK * D) / 256, 256>>>(x);
    dim3 wsb(32, 8);
    wsplit_kernel<0><<<dim3(32, 32, 1),   wsb>>>(Ws1);
    wsplit_kernel<1><<<dim3(32, 32, 1),   wsb>>>(Ws2);
    wsplit_kernel<2><<<dim3(32, 32, EXP), wsb>>>(W1);
    wsplit_kernel<3><<<dim3(32, 32, EXP), wsb>>>(W2);

    // shared expert
    moe_gemm<0><<<dim3(D / 128, NTOK / BM, 1), 256, GEMM_SMEM>>>(bs1, nullptr, NTOK);
    moe_gemm<1><<<dim3(D / 128, NTOK / BM, 1), 256, GEMM_SMEM>>>(bs2, out, NTOK);

    // routed experts (ceil(2574/256) = 11 row tiles)
    moe_gemm<2><<<dim3(D / 128, (CAP + BM - 1) / BM, EXP), 256, GEMM_SMEM>>>(b1, nullptr, CAP);
    moe_gemm<3><<<dim3(D / 128, (CAP + BM - 1) / BM, EXP), 256, GEMM_SMEM>>>(b2, nullptr, CAP);

    combine_kernel<<<NTOK, 256>>>(out);
}

// round 8
// speedup vs baseline: 1.2043x; 1.2043x over previous
#include <cuda_runtime.h>
#include <cuda_bf16.h>
#include <math.h>
#include <stdint.h>

#define D 1024
#define EXP 7
#define NTOK 8192
#define CAP 2574            // int(8192*2/7*1.1)
#define NSLOTS (EXP*CAP)    // 18018

// ======================= device scratch (no runtime allocation) =======================
// Referenced ONLY from device code (host-side symbol addresses of __device__ vars are invalid).
__device__ alignas(16) __nv_bfloat16 g_x_hi[NTOK * D],  g_x_lo[NTOK * D];
__device__ alignas(16) __nv_bfloat16 g_Hs_hi[NTOK * D], g_Hs_lo[NTOK * D];
__device__ alignas(16) __nv_bfloat16 g_He_hi[NSLOTS * D], g_He_lo[NSLOTS * D];
__device__ alignas(16) __nv_bfloat16 g_W1t_hi[EXP * D * D], g_W1t_lo[EXP * D * D];
__device__ alignas(16) __nv_bfloat16 g_W2t_hi[EXP * D * D], g_W2t_lo[EXP * D * D];
__device__ alignas(16) __nv_bfloat16 g_Ws1t_hi[D * D], g_Ws1t_lo[D * D];
__device__ alignas(16) __nv_bfloat16 g_Ws2t_hi[D * D], g_Ws2t_lo[D * D];
__device__ alignas(16) float g_Oexp[NSLOTS * D];
__device__ int   g_slot_token[NSLOTS];
__device__ int   g_slot_of[NTOK * 2];
__device__ int   g_top[NTOK];
__device__ float g_gate0[NTOK];
__device__ float g_gate1[NTOK];
__device__ int   g_mask[NTOK];

// ======================= helpers (base ISA only: sm_80+) =======================
__device__ __forceinline__ uint32_t smem_to_u32(const void* p) {
    uint32_t a;
    asm("{ .reg .u64 t; cvta.to.shared.u64 t, %1; cvt.u32.u64 %0, t; }" : "=r"(a) : "l"(p));
    return a;
}
__device__ __forceinline__ void ldsm4(uint32_t& r0, uint32_t& r1, uint32_t& r2, uint32_t& r3,
                                      uint32_t addr) {
    asm volatile("ldmatrix.sync.aligned.m8n8.x4.shared.b16 {%0,%1,%2,%3}, [%4];"
                 : "=r"(r0), "=r"(r1), "=r"(r2), "=r"(r3) : "r"(addr));
}
__device__ __forceinline__ void mma16816(float* d, const uint32_t* a, const uint32_t* b) {
    asm volatile(
        "mma.sync.aligned.m16n8k16.row.col.f32.bf16.bf16.f32 "
        "{%0,%1,%2,%3}, {%4,%5,%6,%7}, {%8,%9}, {%0,%1,%2,%3};"
        : "+f"(d[0]), "+f"(d[1]), "+f"(d[2]), "+f"(d[3])
        : "r"(a[0]), "r"(a[1]), "r"(a[2]), "r"(a[3]), "r"(b[0]), "r"(b[1]));
}
__device__ __forceinline__ void cp_async16(uint32_t dst, const void* src, int src_size) {
    asm volatile("cp.async.cg.shared.global [%0], [%1], 16, %2;"
                 :: "r"(dst), "l"(src), "r"(src_size) : "memory");
}
#define CP_COMMIT() asm volatile("cp.async.commit_group;" ::: "memory")
#define CP_WAIT2()  asm volatile("cp.async.wait_group 2;" ::: "memory")

// ======================= router =======================
__global__ void __launch_bounds__(256) router_kernel(
    const float* __restrict__ x, const float* __restrict__ noise,
    const float* __restrict__ Wr, const float* __restrict__ br,
    const float* __restrict__ Wn, const float* __restrict__ bn)
{
    int n = blockIdx.x;
    const float* xr = x + (size_t)n * D;
    float aR[EXP], aN[EXP];
#pragma unroll
    for (int e = 0; e < EXP; e++) { aR[e] = 0.f; aN[e] = 0.f; }
    for (int d = threadIdx.x; d < D; d += 256) {
        float xv = xr[d];
        const float* wr = Wr + d * EXP;
        const float* wn = Wn + d * EXP;
#pragma unroll
        for (int e = 0; e < EXP; e++) {
            aR[e] = fmaf(xv, wr[e], aR[e]);
            aN[e] = fmaf(xv, wn[e], aN[e]);
        }
    }
    __shared__ float wred[8][14];
    int lane = threadIdx.x & 31, warp = threadIdx.x >> 5;
#pragma unroll
    for (int i = 0; i < 14; i++) {
        float v = (i < EXP) ? aR[i] : aN[i - EXP];
#pragma unroll
        for (int o = 16; o > 0; o >>= 1) v += __shfl_down_sync(0xffffffffu, v, o);
        if (lane == 0) wred[warp][i] = v;
    }
    __syncthreads();
    if (threadIdx.x == 0) {
        float logit[EXP];
#pragma unroll
        for (int e = 0; e < EXP; e++) {
            float sR = 0.f, sN = 0.f;
#pragma unroll
            for (int w = 0; w < 8; w++) { sR += wred[w][e]; sN += wred[w][e + EXP]; }
            float z  = sN + bn[e];
            float sp = (z > 20.f) ? z : log1pf(expf(z));
            logit[e] = sR + br[e] + noise[(size_t)n * EXP + e] * sp;
        }
        int e0 = 0; float v0 = logit[0];
#pragma unroll
        for (int e = 1; e < EXP; e++) if (logit[e] > v0) { v0 = logit[e]; e0 = e; }
        int e1 = -1; float v1 = -INFINITY;
#pragma unroll
        for (int e = 0; e < EXP; e++) if (e != e0 && logit[e] > v1) { v1 = logit[e]; e1 = e; }
        float ex = expf(v1 - v0);
        g_top[n]   = e0 | (e1 << 4);
        g_gate0[n] = 1.f / (1.f + ex);
        g_gate1[n] = ex / (1.f + ex);
        g_mask[n]  = (1 << e0) | (1 << e1);
        g_slot_of[2 * n]     = -1;
        g_slot_of[2 * n + 1] = -1;
    }
}

// ======================= slot init =======================
__global__ void init_slots()
{
    int i = blockIdx.x * 256 + threadIdx.x;
    if (i < NSLOTS) g_slot_token[i] = 1 << 30;
}

// ======================= ordered capacity scan (single block) =======================
__global__ void __launch_bounds__(1024) scan_kernel(float* __restrict__ dout, int lbl_idx)
{
    __shared__ int   base[EXP];
    __shared__ float probsum[EXP];
    __shared__ int   cnt[EXP];
    __shared__ int   wcnt[32];
    __shared__ int   woff[32];
    __shared__ int   total_s;
    int tid = threadIdx.x, lane = tid & 31, warp = tid >> 5;
    if (tid < EXP) { base[tid] = 0; probsum[tid] = 0.f; cnt[tid] = 0; }
    __syncthreads();

    for (int tile = 0; tile < NTOK / 1024; tile++) {
        int n  = tile * 1024 + tid;
        int mk = g_mask[n];
        int tp = g_top[n];
        int e0 = tp & 15, e1 = (tp >> 4) & 15;
        atomicAdd(&probsum[e0], g_gate0[n]);
        atomicAdd(&probsum[e1], g_gate1[n]);
        atomicAdd(&cnt[e0], 1);
        atomicAdd(&cnt[e1], 1);
#pragma unroll
        for (int e = 0; e < EXP; e++) {
            int flag = (mk >> e) & 1;
            unsigned bal = __ballot_sync(0xffffffffu, flag != 0);
            if (lane == 0) wcnt[warp] = __popc(bal);
            __syncthreads();
            if (warp == 0) {
                int v = wcnt[lane];
                int inc = v;
#pragma unroll
                for (int o = 1; o < 32; o <<= 1) {
                    int t = __shfl_up_sync(0xffffffffu, inc, o);
                    if (lane >= o) inc += t;
                }
                woff[lane] = inc - v;
                if (lane == 31) total_s = inc;
            }
            __syncthreads();
            if (flag) {
                int pos = base[e] + woff[warp] + __popc(bal & ((1u << lane) - 1u));
                if (pos < CAP) {
                    int slot = e * CAP + pos;
                    g_slot_token[slot] = n;
                    int k = (e == e0) ? 0 : 1;
                    g_slot_of[2 * n + k] = slot;
                }
            }
            __syncthreads();
            if (tid == 0) base[e] += total_s;
            __syncthreads();
        }
    }
    if (tid == 0) {
        float s = 0.f;
#pragma unroll
        for (int e = 0; e < EXP; e++)
            s += (probsum[e] / (float)NTOK) * ((float)cnt[e] / (float)NTOK);
        dout[lbl_idx] = (float)EXP * s;
    }
}

// ======================= split / transpose prep =======================
__global__ void __launch_bounds__(256) split_x_kernel(const float* __restrict__ x)
{
    int i = blockIdx.x * 256 + threadIdx.x;
    if (i < NTOK * D) {
        float v = x[i];
        __nv_bfloat16 h = __float2bfloat16(v);
        g_x_hi[i] = h;
        g_x_lo[i] = __float2bfloat16(v - __bfloat162float(h));
    }
}

// W[m][k][n] fp32 -> Wt[m][n][k] bf16 hi/lo. Destination selected by template (device symbols).
template <int WSEL>
__global__ void __launch_bounds__(256) wsplit_kernel(const float* __restrict__ W)
{
    __nv_bfloat16* hi; __nv_bfloat16* lo;
    if constexpr (WSEL == 0) { hi = g_Ws1t_hi; lo = g_Ws1t_lo; }
    if constexpr (WSEL == 1) { hi = g_Ws2t_hi; lo = g_Ws2t_lo; }
    if constexpr (WSEL == 2) { hi = g_W1t_hi;  lo = g_W1t_lo;  }
    if constexpr (WSEL == 3) { hi = g_W2t_hi;  lo = g_W2t_lo;  }
    __shared__ float t[32][33];
    int m = blockIdx.z;
    const float* Wm = W + (size_t)m * D * D;
    int n0 = blockIdx.x * 32, k0 = blockIdx.y * 32;
    int tx = threadIdx.x, ty = threadIdx.y;
#pragma unroll
    for (int r = 0; r < 4; r++) {
        int k = k0 + ty + r * 8;
        t[ty + r * 8][tx] = Wm[(size_t)k * D + n0 + tx];
    }
    __syncthreads();
#pragma unroll
    for (int r = 0; r < 4; r++) {
        int n = n0 + ty + r * 8;
        int k = k0 + tx;
        float v = t[tx][ty + r * 8];
        __nv_bfloat16 h = __float2bfloat16(v);
        size_t o = (size_t)m * D * D + (size_t)n * D + k;
        hi[o] = h;
        lo[o] = __float2bfloat16(v - __bfloat162float(h));
    }
}

// ======================= HMMA bf16x2-split GEMM (merged shared+expert) =======================
// Block 128x128, K' = 3*1024 in 48 chunks of 64. 3-stage cp.async pipeline.
// 256 threads (2 CTAs/SM via launch_bounds); warp grid 2(M) x 4(N); warp tile 64x32.
// grid = (8, 64, 8): z<7 -> expert z (M=CAP, 21 row tiles); z=7 -> shared (M=NTOK, 64 row tiles).
// PHASE 1: A=x(split, gathered for experts) -> relu -> He[z]/Hs (split)
// PHASE 2: A=He[z]/Hs(split)               ->         g_Oexp[z] / OutF (d_out)
#define NCHUNK 48
#define NSTAGE 3
#define STAGE_BYTES 32768            // A 16KB + B 16KB
#define GEMM_SMEM (NSTAGE * STAGE_BYTES + 1024)
#define ROWTILES_EXP ((CAP + 127) / 128)   // 21
#define ROWTILES_SH  (NTOK / 128)          // 64

template <int PHASE>
__global__ void __launch_bounds__(256, 2) moe_gemm(
    const float* __restrict__ bias_exp, const float* __restrict__ bias_sh,
    float* __restrict__ OutF)
{
    constexpr bool RELU = (PHASE == 1);
    int colTile = blockIdx.x, rowTile = blockIdx.y, z = blockIdx.z;
    bool shared_e = (z == EXP);
    int nRow = shared_e ? ROWTILES_SH : ROWTILES_EXP;
    if (rowTile >= nRow) return;
    int M = shared_e ? NTOK : CAP;

    extern __shared__ char smem[];
    uint32_t smem_base = smem_to_u32(smem);
    int tid = threadIdx.x, wid = tid >> 5, lane = tid & 31;
    int wm = wid & 1, wn = wid >> 1;          // 2 x 4 warp grid; warp tile 64x32

    const __nv_bfloat16 *Ahi, *Alo, *Bhi, *Blo;
    const float* bias;
    __nv_bfloat16 *OutHi = nullptr, *OutLo = nullptr;
    bool gather = false;
    if constexpr (PHASE == 1) {
        Ahi = g_x_hi; Alo = g_x_lo;
        if (shared_e) {
            Bhi = g_Ws1t_hi; Blo = g_Ws1t_lo; bias = bias_sh;
            OutHi = g_Hs_hi; OutLo = g_Hs_lo;
        } else {
            Bhi = g_W1t_hi + (size_t)z * D * D; Blo = g_W1t_lo + (size_t)z * D * D;
            bias = bias_exp + (size_t)z * D;
            OutHi = g_He_hi + (size_t)z * CAP * D; OutLo = g_He_lo + (size_t)z * CAP * D;
            gather = true;
        }
    } else {
        if (shared_e) {
            Ahi = g_Hs_hi; Alo = g_Hs_lo; Bhi = g_Ws2t_hi; Blo = g_Ws2t_lo;
            bias = bias_sh;                      // OutF stays = d_out
        } else {
            Ahi = g_He_hi + (size_t)z * CAP * D; Alo = g_He_lo + (size_t)z * CAP * D;
            Bhi = g_W2t_hi + (size_t)z * D * D;  Blo = g_W2t_lo + (size_t)z * D * D;
            bias = bias_exp + (size_t)z * D;
            OutF = g_Oexp + (size_t)z * CAP * D;
        }
    }

    int* s_rowsrc = (int*)(smem + NSTAGE * STAGE_BYTES);
    if (tid < 128) {
        int gr = rowTile * 128 + tid;
        int src;
        if (gather) {
            int t = (gr < M) ? g_slot_token[z * CAP + gr] : (1 << 30);
            src = ((unsigned)t < (unsigned)NTOK) ? t : -1;
        } else {
            src = (gr < M) ? gr : -1;
        }
        s_rowsrc[tid] = src;
    }
    __syncthreads();

    // ---- stage loader: chunk c into stage buffer buf ----
    auto load_stage = [&](int c, int buf) {
        int seg = c >> 4;                       // 0: hiA*hiB  1: loA*hiB  2: hiA*loB
        int kb  = (c & 15) * 64;
        const __nv_bfloat16* aseg = (seg == 1) ? Alo : Ahi;
        const __nv_bfloat16* bseg = (seg == 2) ? Blo : Bhi;
        uint32_t abase = smem_base + buf * STAGE_BYTES;
        uint32_t bbase = abase + 16384;
#pragma unroll
        for (int i = 0; i < 4; i++) {
            int chunk = i * 256 + tid;
            int row = chunk >> 3, c0 = chunk & 7;
            uint32_t swc = (uint32_t)(c0 ^ (row & 7));
            int src = s_rowsrc[row];
            const void* ap = aseg + (size_t)(src < 0 ? 0 : src) * D + kb + c0 * 8;
            cp_async16(abase + row * 128 + swc * 16, ap, src < 0 ? 0 : 16);
            int n = colTile * 128 + row;
            cp_async16(bbase + row * 128 + swc * 16,
                       bseg + (size_t)n * D + kb + c0 * 8, 16);
        }
    };

    float acc[4][4][4];
#pragma unroll
    for (int mi = 0; mi < 4; mi++)
#pragma unroll
        for (int ni = 0; ni < 4; ni++)
#pragma unroll
            for (int q = 0; q < 4; q++) acc[mi][ni][q] = 0.f;

    load_stage(0, 0); CP_COMMIT();
    load_stage(1, 1); CP_COMMIT();
    load_stage(2, 2); CP_COMMIT();

    int buf = 0;
    for (int c = 0; c < NCHUNK; c++) {
        CP_WAIT2();
        __syncthreads();
        uint32_t abase = smem_base + buf * STAGE_BYTES;
        uint32_t bbase = abase + 16384;
#pragma unroll
        for (int s = 0; s < 4; s++) {
            uint32_t afr[4][4], bfr[4][2];
#pragma unroll
            for (int mi = 0; mi < 4; mi++) {
                int row = wm * 64 + mi * 16 + (lane & 15);
                int kc  = s * 2 + (lane >> 4);
                uint32_t addr = abase + row * 128 + (uint32_t)((kc ^ (row & 7)) << 4);
                ldsm4(afr[mi][0], afr[mi][1], afr[mi][2], afr[mi][3], addr);
            }
#pragma unroll
            for (int nb = 0; nb < 2; nb++) {
                int row = wn * 32 + nb * 16 + ((lane >> 4) & 1) * 8 + (lane & 7);
                int kc  = s * 2 + ((lane >> 3) & 1);
                uint32_t addr = bbase + row * 128 + (uint32_t)((kc ^ (row & 7)) << 4);
                uint32_t q0, q1, q2, q3;
                ldsm4(q0, q1, q2, q3, addr);
                bfr[nb * 2][0] = q0;  bfr[nb * 2][1] = q1;
                bfr[nb * 2 + 1][0] = q2; bfr[nb * 2 + 1][1] = q3;
            }
#pragma unroll
            for (int mi = 0; mi < 4; mi++)
#pragma unroll
                for (int ni = 0; ni < 4; ni++)
                    mma16816(acc[mi][ni], afr[mi], bfr[ni]);
        }
        __syncthreads();
        if (c + NSTAGE < NCHUNK) load_stage(c + NSTAGE, buf);
        CP_COMMIT();
        buf = (buf == NSTAGE - 1) ? 0 : buf + 1;
    }

    // ---- epilogue ----
    int rbase = rowTile * 128 + wm * 64 + (lane >> 2);
    int cbase = colTile * 128 + wn * 32 + (lane & 3) * 2;
#pragma unroll
    for (int mi = 0; mi < 4; mi++) {
#pragma unroll
        for (int ni = 0; ni < 4; ni++) {
            int cc = cbase + ni * 8;
            float b0 = bias[cc], b1 = bias[cc + 1];
            float v00 = acc[mi][ni][0] + b0, v01 = acc[mi][ni][1] + b1;
            float v10 = acc[mi][ni][2] + b0, v11 = acc[mi][ni][3] + b1;
            int r0 = rbase + mi * 16, r1 = r0 + 8;
            if constexpr (RELU) {
                v00 = fmaxf(v00, 0.f); v01 = fmaxf(v01, 0.f);
                v10 = fmaxf(v10, 0.f); v11 = fmaxf(v11, 0.f);
                if (r0 < M) {
                    __nv_bfloat162 h = __floats2bfloat162_rn(v00, v01);
                    __nv_bfloat162 l = __floats2bfloat162_rn(
                        v00 - __bfloat162float(__low2bfloat16(h)),
                        v01 - __bfloat162float(__high2bfloat16(h)));
                    *(__nv_bfloat162*)(OutHi + (size_t)r0 * D + cc) = h;
                    *(__nv_bfloat162*)(OutLo + (size_t)r0 * D + cc) = l;
                }
                if (r1 < M) {
                    __nv_bfloat162 h = __floats2bfloat162_rn(v10, v11);
                    __nv_bfloat162 l = __floats2bfloat162_rn(
                        v10 - __bfloat162float(__low2bfloat16(h)),
                        v11 - __bfloat162float(__high2bfloat16(h)));
                    *(__nv_bfloat162*)(OutHi + (size_t)r1 * D + cc) = h;
                    *(__nv_bfloat162*)(OutLo + (size_t)r1 * D + cc) = l;
                }
            } else {
                if (r0 < M) *(float2*)(OutF + (size_t)r0 * D + cc) = make_float2(v00, v01);
                if (r1 < M) *(float2*)(OutF + (size_t)r1 * D + cc) = make_float2(v10, v11);
            }
        }
    }
}

// ======================= combine =======================
__global__ void __launch_bounds__(256) combine_kernel(float* __restrict__ out)
{
    int n = blockIdx.x;
    int s0 = g_slot_of[2 * n], s1 = g_slot_of[2 * n + 1];
    float g0 = g_gate0[n], g1 = g_gate1[n];
    float4* orow = (float4*)(out + (size_t)n * D);
    float4 v = orow[threadIdx.x];
    if (s0 >= 0) {
        float4 e = ((const float4*)(g_Oexp + (size_t)s0 * D))[threadIdx.x];
        v.x += g0 * e.x; v.y += g0 * e.y; v.z += g0 * e.z; v.w += g0 * e.w;
    }
    if (s1 >= 0) {
        float4 e = ((const float4*)(g_Oexp + (size_t)s1 * D))[threadIdx.x];
        v.x += g1 * e.x; v.y += g1 * e.y; v.z += g1 * e.z; v.w += g1 * e.w;
    }
    orow[threadIdx.x] = v;
}

// ======================= launch =======================
extern "C" void kernel_launch(void* const* d_in, const int* in_sizes, int n_in,
                              void* d_out, int out_size)
{
    const float* x     = (const float*)d_in[0];
    const float* noise = (const float*)d_in[1];
    const float* Wr    = (const float*)d_in[2];
    const float* br    = (const float*)d_in[3];
    const float* Wn    = (const float*)d_in[4];
    const float* bn    = (const float*)d_in[5];
    const float* W1    = (const float*)d_in[6];
    const float* b1    = (const float*)d_in[7];
    const float* W2    = (const float*)d_in[8];
    const float* b2    = (const float*)d_in[9];
    const float* Ws1   = (const float*)d_in[10];
    const float* bs1   = (const float*)d_in[11];
    const float* Ws2   = (const float*)d_in[12];
    const float* bs2   = (const float*)d_in[13];
    float* out = (float*)d_out;

    cudaFuncSetAttribute(moe_gemm<1>, cudaFuncAttributeMaxDynamicSharedMemorySize, GEMM_SMEM);
    cudaFuncSetAttribute(moe_gemm<2>, cudaFuncAttributeMaxDynamicSharedMemorySize, GEMM_SMEM);

    router_kernel<<<NTOK, 256>>>(x, noise, Wr, br, Wn, bn);
    init_slots<<<(NSLOTS + 255) / 256, 256>>>();
    scan_kernel<<<1, 1024>>>(out, out_size - 1);

    split_x_kernel<<<(NTOK * D) / 256, 256>>>(x);
    dim3 wsb(32, 8);
    wsplit_kernel<0><<<dim3(32, 32, 1),   wsb>>>(Ws1);
    wsplit_kernel<1><<<dim3(32, 32, 1),   wsb>>>(Ws2);
    wsplit_kernel<2><<<dim3(32, 32, EXP), wsb>>>(W1);
    wsplit_kernel<3><<<dim3(32, 32, EXP), wsb>>>(W2);

    // FFN1 (experts z=0..6 + shared z=7), then FFN2
    moe_gemm<1><<<dim3(D / 128, ROWTILES_SH, EXP + 1), 256, GEMM_SMEM>>>(b1, bs1, nullptr);
    moe_gemm<2><<<dim3(D / 128, ROWTILES_SH, EXP + 1), 256, GEMM_SMEM>>>(b2, bs2, out);

    combine_kernel<<<NTOK, 256>>>(out);
}

// round 9
// speedup vs baseline: 1.6234x; 1.3480x over previous
#include <cuda_runtime.h>
#include <cuda_fp16.h>
#include <math.h>
#include <stdint.h>

#define D 1024
#define EXP 7
#define NTOK 8192
#define CAP 2574            // int(8192*2/7*1.1)
#define NSLOTS (EXP*CAP)    // 18018

// ======================= device scratch (no runtime allocation) =======================
// Referenced ONLY from device code (host-side symbol addresses of __device__ vars are invalid).
__device__ alignas(16) __half g_x_hi[NTOK * D],  g_x_lo[NTOK * D];
__device__ alignas(16) __half g_Hs_hi[NTOK * D], g_Hs_lo[NTOK * D];
__device__ alignas(16) __half g_He_hi[NSLOTS * D], g_He_lo[NSLOTS * D];
__device__ alignas(16) __half g_W1t[EXP * D * D];
__device__ alignas(16) __half g_W2t[EXP * D * D];
__device__ alignas(16) __half g_Ws1t[D * D];
__device__ alignas(16) __half g_Ws2t[D * D];
__device__ alignas(16) float g_Oexp[NSLOTS * D];
__device__ int   g_slot_token[NSLOTS];
__device__ int   g_slot_of[NTOK * 2];
__device__ int   g_top[NTOK];
__device__ float g_gate0[NTOK];
__device__ float g_gate1[NTOK];
__device__ int   g_mask[NTOK];

// ======================= helpers (base ISA only: sm_80+) =======================
__device__ __forceinline__ uint32_t smem_to_u32(const void* p) {
    uint32_t a;
    asm("{ .reg .u64 t; cvta.to.shared.u64 t, %1; cvt.u32.u64 %0, t; }" : "=r"(a) : "l"(p));
    return a;
}
__device__ __forceinline__ void ldsm4(uint32_t& r0, uint32_t& r1, uint32_t& r2, uint32_t& r3,
                                      uint32_t addr) {
    asm volatile("ldmatrix.sync.aligned.m8n8.x4.shared.b16 {%0,%1,%2,%3}, [%4];"
                 : "=r"(r0), "=r"(r1), "=r"(r2), "=r"(r3) : "r"(addr));
}
__device__ __forceinline__ void mma16816(float* d, const uint32_t* a, const uint32_t* b) {
    asm volatile(
        "mma.sync.aligned.m16n8k16.row.col.f32.f16.f16.f32 "
        "{%0,%1,%2,%3}, {%4,%5,%6,%7}, {%8,%9}, {%0,%1,%2,%3};"
        : "+f"(d[0]), "+f"(d[1]), "+f"(d[2]), "+f"(d[3])
        : "r"(a[0]), "r"(a[1]), "r"(a[2]), "r"(a[3]), "r"(b[0]), "r"(b[1]));
}
__device__ __forceinline__ void cp_async16(uint32_t dst, const void* src, int src_size) {
    asm volatile("cp.async.cg.shared.global [%0], [%1], 16, %2;"
                 :: "r"(dst), "l"(src), "r"(src_size) : "memory");
}
#define CP_COMMIT() asm volatile("cp.async.commit_group;" ::: "memory")
#define CP_WAIT1()  asm volatile("cp.async.wait_group 1;" ::: "memory")

// ======================= router =======================
__global__ void __launch_bounds__(256) router_kernel(
    const float* __restrict__ x, const float* __restrict__ noise,
    const float* __restrict__ Wr, const float* __restrict__ br,
    const float* __restrict__ Wn, const float* __restrict__ bn)
{
    int n = blockIdx.x;
    const float* xr = x + (size_t)n * D;
    float aR[EXP], aN[EXP];
#pragma unroll
    for (int e = 0; e < EXP; e++) { aR[e] = 0.f; aN[e] = 0.f; }
    for (int d = threadIdx.x; d < D; d += 256) {
        float xv = xr[d];
        const float* wr = Wr + d * EXP;
        const float* wn = Wn + d * EXP;
#pragma unroll
        for (int e = 0; e < EXP; e++) {
            aR[e] = fmaf(xv, wr[e], aR[e]);
            aN[e] = fmaf(xv, wn[e], aN[e]);
        }
    }
    __shared__ float wred[8][14];
    int lane = threadIdx.x & 31, warp = threadIdx.x >> 5;
#pragma unroll
    for (int i = 0; i < 14; i++) {
        float v = (i < EXP) ? aR[i] : aN[i - EXP];
#pragma unroll
        for (int o = 16; o > 0; o >>= 1) v += __shfl_down_sync(0xffffffffu, v, o);
        if (lane == 0) wred[warp][i] = v;
    }
    __syncthreads();
    if (threadIdx.x == 0) {
        float logit[EXP];
#pragma unroll
        for (int e = 0; e < EXP; e++) {
            float sR = 0.f, sN = 0.f;
#pragma unroll
            for (int w = 0; w < 8; w++) { sR += wred[w][e]; sN += wred[w][e + EXP]; }
            float z  = sN + bn[e];
            float sp = (z > 20.f) ? z : log1pf(expf(z));
            logit[e] = sR + br[e] + noise[(size_t)n * EXP + e] * sp;
        }
        int e0 = 0; float v0 = logit[0];
#pragma unroll
        for (int e = 1; e < EXP; e++) if (logit[e] > v0) { v0 = logit[e]; e0 = e; }
        int e1 = -1; float v1 = -INFINITY;
#pragma unroll
        for (int e = 0; e < EXP; e++) if (e != e0 && logit[e] > v1) { v1 = logit[e]; e1 = e; }
        float ex = expf(v1 - v0);
        g_top[n]   = e0 | (e1 << 4);
        g_gate0[n] = 1.f / (1.f + ex);
        g_gate1[n] = ex / (1.f + ex);
        g_mask[n]  = (1 << e0) | (1 << e1);
        g_slot_of[2 * n]     = -1;
        g_slot_of[2 * n + 1] = -1;
    }
}

// ======================= slot init =======================
__global__ void init_slots()
{
    int i = blockIdx.x * 256 + threadIdx.x;
    if (i < NSLOTS) g_slot_token[i] = 1 << 30;
}

// ======================= ordered capacity scan (single block) =======================
__global__ void __launch_bounds__(1024) scan_kernel(float* __restrict__ dout, int lbl_idx)
{
    __shared__ int   base[EXP];
    __shared__ float probsum[EXP];
    __shared__ int   cnt[EXP];
    __shared__ int   wcnt[32];
    __shared__ int   woff[32];
    __shared__ int   total_s;
    int tid = threadIdx.x, lane = tid & 31, warp = tid >> 5;
    if (tid < EXP) { base[tid] = 0; probsum[tid] = 0.f; cnt[tid] = 0; }
    __syncthreads();

    for (int tile = 0; tile < NTOK / 1024; tile++) {
        int n  = tile * 1024 + tid;
        int mk = g_mask[n];
        int tp = g_top[n];
        int e0 = tp & 15, e1 = (tp >> 4) & 15;
        atomicAdd(&probsum[e0], g_gate0[n]);
        atomicAdd(&probsum[e1], g_gate1[n]);
        atomicAdd(&cnt[e0], 1);
        atomicAdd(&cnt[e1], 1);
#pragma unroll
        for (int e = 0; e < EXP; e++) {
            int flag = (mk >> e) & 1;
            unsigned bal = __ballot_sync(0xffffffffu, flag != 0);
            if (lane == 0) wcnt[warp] = __popc(bal);
            __syncthreads();
            if (warp == 0) {
                int v = wcnt[lane];
                int inc = v;
#pragma unroll
                for (int o = 1; o < 32; o <<= 1) {
                    int t = __shfl_up_sync(0xffffffffu, inc, o);
                    if (lane >= o) inc += t;
                }
                woff[lane] = inc - v;
                if (lane == 31) total_s = inc;
            }
            __syncthreads();
            if (flag) {
                int pos = base[e] + woff[warp] + __popc(bal & ((1u << lane) - 1u));
                if (pos < CAP) {
                    int slot = e * CAP + pos;
                    g_slot_token[slot] = n;
                    int k = (e == e0) ? 0 : 1;
                    g_slot_of[2 * n + k] = slot;
                }
            }
            __syncthreads();
            if (tid == 0) base[e] += total_s;
            __syncthreads();
        }
    }
    if (tid == 0) {
        float s = 0.f;
#pragma unroll
        for (int e = 0; e < EXP; e++)
            s += (probsum[e] / (float)NTOK) * ((float)cnt[e] / (float)NTOK);
        dout[lbl_idx] = (float)EXP * s;
    }
}

// ======================= split / transpose prep =======================
__global__ void __launch_bounds__(256) split_x_kernel(const float* __restrict__ x)
{
    int i = blockIdx.x * 256 + threadIdx.x;
    if (i < NTOK * D) {
        float v = x[i];
        __half h = __float2half(v);
        g_x_hi[i] = h;
        g_x_lo[i] = __float2half(v - __half2float(h));
    }
}

// W[m][k][n] fp32 -> Wt[m][n][k] fp16. Destination selected by template (device symbols).
template <int WSEL>
__global__ void __launch_bounds__(256) wsplit_kernel(const float* __restrict__ W)
{
    __half* hi;
    if constexpr (WSEL == 0) { hi = g_Ws1t; }
    if constexpr (WSEL == 1) { hi = g_Ws2t; }
    if constexpr (WSEL == 2) { hi = g_W1t;  }
    if constexpr (WSEL == 3) { hi = g_W2t;  }
    __shared__ float t[32][33];
    int m = blockIdx.z;
    const float* Wm = W + (size_t)m * D * D;
    int n0 = blockIdx.x * 32, k0 = blockIdx.y * 32;
    int tx = threadIdx.x, ty = threadIdx.y;
#pragma unroll
    for (int r = 0; r < 4; r++) {
        int k = k0 + ty + r * 8;
        t[ty + r * 8][tx] = Wm[(size_t)k * D + n0 + tx];
    }
    __syncthreads();
#pragma unroll
    for (int r = 0; r < 4; r++) {
        int n = n0 + ty + r * 8;
        int k = k0 + tx;
        hi[(size_t)m * D * D + (size_t)n * D + k] = __float2half(t[tx][ty + r * 8]);
    }
}

// ======================= HMMA fp16 2-term split GEMM (merged shared+expert) =======================
// Block 128x128, K' = 2*1024 in 32 chunks of 64 (seg0: A_hi*W, seg1: A_lo*W).
// 3-stage cp.async pipeline, ONE barrier per chunk. 256 threads, 2 CTAs/SM.
// Flattened grid: y in [0,147) -> expert z=y/21 row=y%21 ; y in [147,211) -> shared row=y-147.
// PHASE 1: A=x(split, gathered for experts) -> relu -> He[z]/Hs (split fp16)
// PHASE 2: A=He[z]/Hs(split)                ->        g_Oexp[z] / OutF (d_out)
#define NCHUNK 32
#define NSTAGE 3
#define STAGE_BYTES 32768            // A 16KB + B 16KB
#define GEMM_SMEM (NSTAGE * STAGE_BYTES + 1024)
#define ROWTILES_EXP ((CAP + 127) / 128)   // 21
#define ROWTILES_SH  (NTOK / 128)          // 64
#define NYT (EXP * ROWTILES_EXP + ROWTILES_SH)   // 211

template <int PHASE>
__global__ void __launch_bounds__(256, 2) moe_gemm(
    const float* __restrict__ bias_exp, const float* __restrict__ bias_sh,
    float* __restrict__ OutF)
{
    constexpr bool RELU = (PHASE == 1);
    int colTile = blockIdx.x;
    int y = blockIdx.y;
    bool shared_e = (y >= EXP * ROWTILES_EXP);
    int z = shared_e ? EXP : (y / ROWTILES_EXP);
    int rowTile = shared_e ? (y - EXP * ROWTILES_EXP) : (y % ROWTILES_EXP);
    int M = shared_e ? NTOK : CAP;

    extern __shared__ char smem[];
    uint32_t smem_base = smem_to_u32(smem);
    int tid = threadIdx.x, wid = tid >> 5, lane = tid & 31;
    int wm = wid & 1, wn = wid >> 1;          // 2 x 4 warp grid; warp tile 64x32

    const __half *Ahi, *Alo, *B;
    const float* bias;
    __half *OutHi = nullptr, *OutLo = nullptr;
    bool gather = false;
    if constexpr (PHASE == 1) {
        Ahi = g_x_hi; Alo = g_x_lo;
        if (shared_e) {
            B = g_Ws1t; bias = bias_sh;
            OutHi = g_Hs_hi; OutLo = g_Hs_lo;
        } else {
            B = g_W1t + (size_t)z * D * D;
            bias = bias_exp + (size_t)z * D;
            OutHi = g_He_hi + (size_t)z * CAP * D; OutLo = g_He_lo + (size_t)z * CAP * D;
            gather = true;
        }
    } else {
        if (shared_e) {
            Ahi = g_Hs_hi; Alo = g_Hs_lo; B = g_Ws2t;
            bias = bias_sh;                      // OutF stays = d_out
        } else {
            Ahi = g_He_hi + (size_t)z * CAP * D; Alo = g_He_lo + (size_t)z * CAP * D;
            B = g_W2t + (size_t)z * D * D;
            bias = bias_exp + (size_t)z * D;
            OutF = g_Oexp + (size_t)z * CAP * D;
        }
    }

    int* s_rowsrc = (int*)(smem + NSTAGE * STAGE_BYTES);
    if (tid < 128) {
        int gr = rowTile * 128 + tid;
        int src;
        if (gather) {
            int t = (gr < M) ? g_slot_token[z * CAP + gr] : (1 << 30);
            src = ((unsigned)t < (unsigned)NTOK) ? t : -1;
        } else {
            src = (gr < M) ? gr : -1;
        }
        s_rowsrc[tid] = src;
    }
    __syncthreads();

    // ---- stage loader: chunk c into stage buffer buf ----
    auto load_stage = [&](int c, int buf) {
        int seg = c >> 4;                       // 0: A_hi * W   1: A_lo * W
        int kb  = (c & 15) * 64;
        const __half* aseg = (seg == 1) ? Alo : Ahi;
        uint32_t abase = smem_base + buf * STAGE_BYTES;
        uint32_t bbase = abase + 16384;
#pragma unroll
        for (int i = 0; i < 4; i++) {
            int chunk = i * 256 + tid;
            int row = chunk >> 3, c0 = chunk & 7;
            uint32_t swc = (uint32_t)(c0 ^ (row & 7));
            int src = s_rowsrc[row];
            const void* ap = aseg + (size_t)(src < 0 ? 0 : src) * D + kb + c0 * 8;
            cp_async16(abase + row * 128 + swc * 16, ap, src < 0 ? 0 : 16);
            int n = colTile * 128 + row;
            cp_async16(bbase + row * 128 + swc * 16,
                       B + (size_t)n * D + kb + c0 * 8, 16);
        }
    };

    float acc[4][4][4];
#pragma unroll
    for (int mi = 0; mi < 4; mi++)
#pragma unroll
        for (int ni = 0; ni < 4; ni++)
#pragma unroll
            for (int q = 0; q < 4; q++) acc[mi][ni][q] = 0.f;

    load_stage(0, 0); CP_COMMIT();
    load_stage(1, 1); CP_COMMIT();

    for (int c = 0; c < NCHUNK; c++) {
        int buf = c % NSTAGE;
        CP_WAIT1();            // chunk c complete (chunk c+1 may be in flight)
        __syncthreads();       // data visible to all warps; prior reads of buffer (c+2)%3 done
        if (c + 2 < NCHUNK) load_stage(c + 2, (c + 2) % NSTAGE);
        CP_COMMIT();
        uint32_t abase = smem_base + buf * STAGE_BYTES;
        uint32_t bbase = abase + 16384;
#pragma unroll
        for (int s = 0; s < 4; s++) {
            uint32_t afr[4][4], bfr[4][2];
#pragma unroll
            for (int mi = 0; mi < 4; mi++) {
                int row = wm * 64 + mi * 16 + (lane & 15);
                int kc  = s * 2 + (lane >> 4);
                uint32_t addr = abase + row * 128 + (uint32_t)((kc ^ (row & 7)) << 4);
                ldsm4(afr[mi][0], afr[mi][1], afr[mi][2], afr[mi][3], addr);
            }
#pragma unroll
            for (int nb = 0; nb < 2; nb++) {
                int row = wn * 32 + nb * 16 + ((lane >> 4) & 1) * 8 + (lane & 7);
                int kc  = s * 2 + ((lane >> 3) & 1);
                uint32_t addr = bbase + row * 128 + (uint32_t)((kc ^ (row & 7)) << 4);
                uint32_t q0, q1, q2, q3;
                ldsm4(q0, q1, q2, q3, addr);
                bfr[nb * 2][0] = q0;  bfr[nb * 2][1] = q1;
                bfr[nb * 2 + 1][0] = q2; bfr[nb * 2 + 1][1] = q3;
            }
#pragma unroll
            for (int mi = 0; mi < 4; mi++)
#pragma unroll
                for (int ni = 0; ni < 4; ni++)
                    mma16816(acc[mi][ni], afr[mi], bfr[ni]);
        }
    }

    // ---- epilogue ----
    int rbase = rowTile * 128 + wm * 64 + (lane >> 2);
    int cbase = colTile * 128 + wn * 32 + (lane & 3) * 2;
#pragma unroll
    for (int mi = 0; mi < 4; mi++) {
#pragma unroll
        for (int ni = 0; ni < 4; ni++) {
            int cc = cbase + ni * 8;
            float b0 = bias[cc], b1 = bias[cc + 1];
            float v00 = acc[mi][ni][0] + b0, v01 = acc[mi][ni][1] + b1;
            float v10 = acc[mi][ni][2] + b0, v11 = acc[mi][ni][3] + b1;
            int r0 = rbase + mi * 16, r1 = r0 + 8;
            if constexpr (RELU) {
                v00 = fmaxf(v00, 0.f); v01 = fmaxf(v01, 0.f);
                v10 = fmaxf(v10, 0.f); v11 = fmaxf(v11, 0.f);
                if (r0 < M) {
                    __half2 h = __floats2half2_rn(v00, v01);
                    __half2 l = __floats2half2_rn(
                        v00 - __half2float(__low2half(h)),
                        v01 - __half2float(__high2half(h)));
                    *(__half2*)(OutHi + (size_t)r0 * D + cc) = h;
                    *(__half2*)(OutLo + (size_t)r0 * D + cc) = l;
                }
                if (r1 < M) {
                    __half2 h = __floats2half2_rn(v10, v11);
                    __half2 l = __floats2half2_rn(
                        v10 - __half2float(__low2half(h)),
                        v11 - __half2float(__high2half(h)));
                    *(__half2*)(OutHi + (size_t)r1 * D + cc) = h;
                    *(__half2*)(OutLo + (size_t)r1 * D + cc) = l;
                }
            } else {
                if (r0 < M) *(float2*)(OutF + (size_t)r0 * D + cc) = make_float2(v00, v01);
                if (r1 < M) *(float2*)(OutF + (size_t)r1 * D + cc) = make_float2(v10, v11);
            }
        }
    }
}

// ======================= combine =======================
__global__ void __launch_bounds__(256) combine_kernel(float* __restrict__ out)
{
    int n = blockIdx.x;
    int s0 = g_slot_of[2 * n], s1 = g_slot_of[2 * n + 1];
    float g0 = g_gate0[n], g1 = g_gate1[n];
    float4* orow = (float4*)(out + (size_t)n * D);
    float4 v = orow[threadIdx.x];
    if (s0 >= 0) {
        float4 e = ((const float4*)(g_Oexp + (size_t)s0 * D))[threadIdx.x];
        v.x += g0 * e.x; v.y += g0 * e.y; v.z += g0 * e.z; v.w += g0 * e.w;
    }
    if (s1 >= 0) {
        float4 e = ((const float4*)(g_Oexp + (size_t)s1 * D))[threadIdx.x];
        v.x += g1 * e.x; v.y += g1 * e.y; v.z += g1 * e.z; v.w += g1 * e.w;
    }
    orow[threadIdx.x] = v;
}

// ======================= launch =======================
extern "C" void kernel_launch(void* const* d_in, const int* in_sizes, int n_in,
                              void* d_out, int out_size)
{
    const float* x     = (const float*)d_in[0];
    const float* noise = (const float*)d_in[1];
    const float* Wr    = (const float*)d_in[2];
    const float* br    = (const float*)d_in[3];
    const float* Wn    = (const float*)d_in[4];
    const float* bn    = (const float*)d_in[5];
    const float* W1    = (const float*)d_in[6];
    const float* b1    = (const float*)d_in[7];
    const float* W2    = (const float*)d_in[8];
    const float* b2    = (const float*)d_in[9];
    const float* Ws1   = (const float*)d_in[10];
    const float* bs1   = (const float*)d_in[11];
    const float* Ws2   = (const float*)d_in[12];
    const float* bs2   = (const float*)d_in[13];
    float* out = (float*)d_out;

    cudaFuncSetAttribute(moe_gemm<1>, cudaFuncAttributeMaxDynamicSharedMemorySize, GEMM_SMEM);
    cudaFuncSetAttribute(moe_gemm<2>, cudaFuncAttributeMaxDynamicSharedMemorySize, GEMM_SMEM);

    router_kernel<<<NTOK, 256>>>(x, noise, Wr, br, Wn, bn);
    init_slots<<<(NSLOTS + 255) / 256, 256>>>();
    scan_kernel<<<1, 1024>>>(out, out_size - 1);

    split_x_kernel<<<(NTOK * D) / 256, 256>>>(x);
    dim3 wsb(32, 8);
    wsplit_kernel<0><<<dim3(32, 32, 1),   wsb>>>(Ws1);
    wsplit_kernel<1><<<dim3(32, 32, 1),   wsb>>>(Ws2);
    wsplit_kernel<2><<<dim3(32, 32, EXP), wsb>>>(W1);
    wsplit_kernel<3><<<dim3(32, 32, EXP), wsb>>>(W2);

    // FFN1 (experts + shared, flattened grid), then FFN2
    moe_gemm<1><<<dim3(D / 128, NYT), 256, GEMM_SMEM>>>(b1, bs1, nullptr);
    moe_gemm<2><<<dim3(D / 128, NYT), 256, GEMM_SMEM>>>(b2, bs2, out);

    combine_kernel<<<NTOK, 256>>>(out);
}

// round 10
// speedup vs baseline: 2.5418x; 1.5657x over previous
#include <cuda_runtime.h>
#include <cuda_fp16.h>
#include <math.h>
#include <stdint.h>

#define D 1024
#define EXP 7
#define NTOK 8192
#define CAP 2574            // int(8192*2/7*1.1)
#define NSLOTS (EXP*CAP)    // 18018

// ======================= device scratch (no runtime allocation) =======================
// Referenced ONLY from device code (host-side symbol addresses of __device__ vars are invalid).
__device__ alignas(16) __half g_x16[NTOK * D];
__device__ alignas(16) __half g_Hs[NTOK * D];
__device__ alignas(16) __half g_He[NSLOTS * D];
__device__ alignas(16) __half g_W1t[EXP * D * D];
__device__ alignas(16) __half g_W2t[EXP * D * D];
__device__ alignas(16) __half g_Ws1t[D * D];
__device__ alignas(16) __half g_Ws2t[D * D];
__device__ alignas(16) float g_Oexp[NSLOTS * D];
__device__ int   g_slot_token[NSLOTS];
__device__ int   g_slot_of[NTOK * 2];
__device__ int   g_top[NTOK];
__device__ float g_gate0[NTOK];
__device__ float g_gate1[NTOK];
__device__ int   g_mask[NTOK];

// ======================= helpers (base ISA only: sm_80+) =======================
__device__ __forceinline__ uint32_t smem_to_u32(const void* p) {
    uint32_t a;
    asm("{ .reg .u64 t; cvta.to.shared.u64 t, %1; cvt.u32.u64 %0, t; }" : "=r"(a) : "l"(p));
    return a;
}
__device__ __forceinline__ void ldsm4(uint32_t& r0, uint32_t& r1, uint32_t& r2, uint32_t& r3,
                                      uint32_t addr) {
    asm volatile("ldmatrix.sync.aligned.m8n8.x4.shared.b16 {%0,%1,%2,%3}, [%4];"
                 : "=r"(r0), "=r"(r1), "=r"(r2), "=r"(r3) : "r"(addr));
}
__device__ __forceinline__ void mma16816(float* d, const uint32_t* a, const uint32_t* b) {
    asm volatile(
        "mma.sync.aligned.m16n8k16.row.col.f32.f16.f16.f32 "
        "{%0,%1,%2,%3}, {%4,%5,%6,%7}, {%8,%9}, {%0,%1,%2,%3};"
        : "+f"(d[0]), "+f"(d[1]), "+f"(d[2]), "+f"(d[3])
        : "r"(a[0]), "r"(a[1]), "r"(a[2]), "r"(a[3]), "r"(b[0]), "r"(b[1]));
}
__device__ __forceinline__ void cp_async16(uint32_t dst, const void* src, int src_size) {
    asm volatile("cp.async.cg.shared.global [%0], [%1], 16, %2;"
                 :: "r"(dst), "l"(src), "r"(src_size) : "memory");
}
#define CP_COMMIT() asm volatile("cp.async.commit_group;" ::: "memory")
#define CP_WAIT1()  asm volatile("cp.async.wait_group 1;" ::: "memory")

// ======================= router =======================
__global__ void __launch_bounds__(256) router_kernel(
    const float* __restrict__ x, const float* __restrict__ noise,
    const float* __restrict__ Wr, const float* __restrict__ br,
    const float* __restrict__ Wn, const float* __restrict__ bn)
{
    int n = blockIdx.x;
    const float* xr = x + (size_t)n * D;
    float aR[EXP], aN[EXP];
#pragma unroll
    for (int e = 0; e < EXP; e++) { aR[e] = 0.f; aN[e] = 0.f; }
    for (int d = threadIdx.x; d < D; d += 256) {
        float xv = xr[d];
        const float* wr = Wr + d * EXP;
        const float* wn = Wn + d * EXP;
#pragma unroll
        for (int e = 0; e < EXP; e++) {
            aR[e] = fmaf(xv, wr[e], aR[e]);
            aN[e] = fmaf(xv, wn[e], aN[e]);
        }
    }
    __shared__ float wred[8][14];
    int lane = threadIdx.x & 31, warp = threadIdx.x >> 5;
#pragma unroll
    for (int i = 0; i < 14; i++) {
        float v = (i < EXP) ? aR[i] : aN[i - EXP];
#pragma unroll
        for (int o = 16; o > 0; o >>= 1) v += __shfl_down_sync(0xffffffffu, v, o);
        if (lane == 0) wred[warp][i] = v;
    }
    __syncthreads();
    if (threadIdx.x == 0) {
        float logit[EXP];
#pragma unroll
        for (int e = 0; e < EXP; e++) {
            float sR = 0.f, sN = 0.f;
#pragma unroll
            for (int w = 0; w < 8; w++) { sR += wred[w][e]; sN += wred[w][e + EXP]; }
            float z  = sN + bn[e];
            float sp = (z > 20.f) ? z : log1pf(expf(z));
            logit[e] = sR + br[e] + noise[(size_t)n * EXP + e] * sp;
        }
        int e0 = 0; float v0 = logit[0];
#pragma unroll
        for (int e = 1; e < EXP; e++) if (logit[e] > v0) { v0 = logit[e]; e0 = e; }
        int e1 = -1; float v1 = -INFINITY;
#pragma unroll
        for (int e = 0; e < EXP; e++) if (e != e0 && logit[e] > v1) { v1 = logit[e]; e1 = e; }
        float ex = expf(v1 - v0);
        g_top[n]   = e0 | (e1 << 4);
        g_gate0[n] = 1.f / (1.f + ex);
        g_gate1[n] = ex / (1.f + ex);
        g_mask[n]  = (1 << e0) | (1 << e1);
        g_slot_of[2 * n]     = -1;
        g_slot_of[2 * n + 1] = -1;
    }
}

// ======================= slot init =======================
__global__ void init_slots()
{
    int i = blockIdx.x * 256 + threadIdx.x;
    if (i < NSLOTS) g_slot_token[i] = 1 << 30;
}

// ======================= ordered capacity scan (single block) =======================
__global__ void __launch_bounds__(1024) scan_kernel(float* __restrict__ dout, int lbl_idx)
{
    __shared__ int   base[EXP];
    __shared__ float probsum[EXP];
    __shared__ int   cnt[EXP];
    __shared__ int   wcnt[32];
    __shared__ int   woff[32];
    __shared__ int   total_s;
    int tid = threadIdx.x, lane = tid & 31, warp = tid >> 5;
    if (tid < EXP) { base[tid] = 0; probsum[tid] = 0.f; cnt[tid] = 0; }
    __syncthreads();

    for (int tile = 0; tile < NTOK / 1024; tile++) {
        int n  = tile * 1024 + tid;
        int mk = g_mask[n];
        int tp = g_top[n];
        int e0 = tp & 15, e1 = (tp >> 4) & 15;
        atomicAdd(&probsum[e0], g_gate0[n]);
        atomicAdd(&probsum[e1], g_gate1[n]);
        atomicAdd(&cnt[e0], 1);
        atomicAdd(&cnt[e1], 1);
#pragma unroll
        for (int e = 0; e < EXP; e++) {
            int flag = (mk >> e) & 1;
            unsigned bal = __ballot_sync(0xffffffffu, flag != 0);
            if (lane == 0) wcnt[warp] = __popc(bal);
            __syncthreads();
            if (warp == 0) {
                int v = wcnt[lane];
                int inc = v;
#pragma unroll
                for (int o = 1; o < 32; o <<= 1) {
                    int t = __shfl_up_sync(0xffffffffu, inc, o);
                    if (lane >= o) inc += t;
                }
                woff[lane] = inc - v;
                if (lane == 31) total_s = inc;
            }
            __syncthreads();
            if (flag) {
                int pos = base[e] + woff[warp] + __popc(bal & ((1u << lane) - 1u));
                if (pos < CAP) {
                    int slot = e * CAP + pos;
                    g_slot_token[slot] = n;
                    int k = (e == e0) ? 0 : 1;
                    g_slot_of[2 * n + k] = slot;
                }
            }
            __syncthreads();
            if (tid == 0) base[e] += total_s;
            __syncthreads();
        }
    }
    if (tid == 0) {
        float s = 0.f;
#pragma unroll
        for (int e = 0; e < EXP; e++)
            s += (probsum[e] / (float)NTOK) * ((float)cnt[e] / (float)NTOK);
        dout[lbl_idx] = (float)EXP * s;
    }
}

// ======================= convert / transpose prep =======================
__global__ void __launch_bounds__(256) split_x_kernel(const float* __restrict__ x)
{
    int i = blockIdx.x * 256 + threadIdx.x;
    if (i < NTOK * D) g_x16[i] = __float2half(x[i]);
}

// W[m][k][n] fp32 -> Wt[m][n][k] fp16. Destination selected by template (device symbols).
template <int WSEL>
__global__ void __launch_bounds__(256) wsplit_kernel(const float* __restrict__ W)
{
    __half* hi;
    if constexpr (WSEL == 0) { hi = g_Ws1t; }
    if constexpr (WSEL == 1) { hi = g_Ws2t; }
    if constexpr (WSEL == 2) { hi = g_W1t;  }
    if constexpr (WSEL == 3) { hi = g_W2t;  }
    __shared__ float t[32][33];
    int m = blockIdx.z;
    const float* Wm = W + (size_t)m * D * D;
    int n0 = blockIdx.x * 32, k0 = blockIdx.y * 32;
    int tx = threadIdx.x, ty = threadIdx.y;
#pragma unroll
    for (int r = 0; r < 4; r++) {
        int k = k0 + ty + r * 8;
        t[ty + r * 8][tx] = Wm[(size_t)k * D + n0 + tx];
    }
    __syncthreads();
#pragma unroll
    for (int r = 0; r < 4; r++) {
        int n = n0 + ty + r * 8;
        int k = k0 + tx;
        hi[(size_t)m * D * D + (size_t)n * D + k] = __float2half(t[tx][ty + r * 8]);
    }
}

// ======================= HMMA fp16 GEMM (merged shared+expert) =======================
// Block 128x128, K = 1024 in 16 chunks of 64. fp32 accumulate.
// 3-stage cp.async pipeline, ONE barrier per chunk. 256 threads, 2 CTAs/SM.
// Flattened grid: y in [0,147) -> expert z=y/21 row=y%21 ; y in [147,211) -> shared row=y-147.
// PHASE 1: A=x16(gathered for experts) -> relu -> He[z]/Hs (fp16)
// PHASE 2: A=He[z]/Hs                  ->        g_Oexp[z] / OutF (d_out)
#define NCHUNK 16
#define NSTAGE 3
#define STAGE_BYTES 32768            // A 16KB + B 16KB
#define GEMM_SMEM (NSTAGE * STAGE_BYTES + 1024)
#define ROWTILES_EXP ((CAP + 127) / 128)   // 21
#define ROWTILES_SH  (NTOK / 128)          // 64
#define NYT (EXP * ROWTILES_EXP + ROWTILES_SH)   // 211

template <int PHASE>
__global__ void __launch_bounds__(256, 2) moe_gemm(
    const float* __restrict__ bias_exp, const float* __restrict__ bias_sh,
    float* __restrict__ OutF)
{
    constexpr bool RELU = (PHASE == 1);
    int colTile = blockIdx.x;
    int y = blockIdx.y;
    bool shared_e = (y >= EXP * ROWTILES_EXP);
    int z = shared_e ? EXP : (y / ROWTILES_EXP);
    int rowTile = shared_e ? (y - EXP * ROWTILES_EXP) : (y % ROWTILES_EXP);
    int M = shared_e ? NTOK : CAP;

    extern __shared__ char smem[];
    uint32_t smem_base = smem_to_u32(smem);
    int tid = threadIdx.x, wid = tid >> 5, lane = tid & 31;
    int wm = wid & 1, wn = wid >> 1;          // 2 x 4 warp grid; warp tile 64x32

    const __half *A, *B;
    const float* bias;
    __half *OutH = nullptr;
    bool gather = false;
    if constexpr (PHASE == 1) {
        A = g_x16;
        if (shared_e) {
            B = g_Ws1t; bias = bias_sh;
            OutH = g_Hs;
        } else {
            B = g_W1t + (size_t)z * D * D;
            bias = bias_exp + (size_t)z * D;
            OutH = g_He + (size_t)z * CAP * D;
            gather = true;
        }
    } else {
        if (shared_e) {
            A = g_Hs; B = g_Ws2t;
            bias = bias_sh;                      // OutF stays = d_out
        } else {
            A = g_He + (size_t)z * CAP * D;
            B = g_W2t + (size_t)z * D * D;
            bias = bias_exp + (size_t)z * D;
            OutF = g_Oexp + (size_t)z * CAP * D;
        }
    }

    int* s_rowsrc = (int*)(smem + NSTAGE * STAGE_BYTES);
    if (tid < 128) {
        int gr = rowTile * 128 + tid;
        int src;
        if (gather) {
            int t = (gr < M) ? g_slot_token[z * CAP + gr] : (1 << 30);
            src = ((unsigned)t < (unsigned)NTOK) ? t : -1;
        } else {
            src = (gr < M) ? gr : -1;
        }
        s_rowsrc[tid] = src;
    }
    __syncthreads();

    // ---- stage loader: chunk c into stage buffer buf ----
    auto load_stage = [&](int c, int buf) {
        int kb = c * 64;
        uint32_t abase = smem_base + buf * STAGE_BYTES;
        uint32_t bbase = abase + 16384;
#pragma unroll
        for (int i = 0; i < 4; i++) {
            int chunk = i * 256 + tid;
            int row = chunk >> 3, c0 = chunk & 7;
            uint32_t swc = (uint32_t)(c0 ^ (row & 7));
            int src = s_rowsrc[row];
            const void* ap = A + (size_t)(src < 0 ? 0 : src) * D + kb + c0 * 8;
            cp_async16(abase + row * 128 + swc * 16, ap, src < 0 ? 0 : 16);
            int n = colTile * 128 + row;
            cp_async16(bbase + row * 128 + swc * 16,
                       B + (size_t)n * D + kb + c0 * 8, 16);
        }
    };

    float acc[4][4][4];
#pragma unroll
    for (int mi = 0; mi < 4; mi++)
#pragma unroll
        for (int ni = 0; ni < 4; ni++)
#pragma unroll
            for (int q = 0; q < 4; q++) acc[mi][ni][q] = 0.f;

    load_stage(0, 0); CP_COMMIT();
    load_stage(1, 1); CP_COMMIT();

    for (int c = 0; c < NCHUNK; c++) {
        int buf = c % NSTAGE;
        CP_WAIT1();            // chunk c complete (chunk c+1 may be in flight)
        __syncthreads();       // data visible to all warps; prior reads of buffer (c+2)%3 done
        if (c + 2 < NCHUNK) load_stage(c + 2, (c + 2) % NSTAGE);
        CP_COMMIT();
        uint32_t abase = smem_base + buf * STAGE_BYTES;
        uint32_t bbase = abase + 16384;
#pragma unroll
        for (int s = 0; s < 4; s++) {
            uint32_t afr[4][4], bfr[4][2];
#pragma unroll
            for (int mi = 0; mi < 4; mi++) {
                int row = wm * 64 + mi * 16 + (lane & 15);
                int kc  = s * 2 + (lane >> 4);
                uint32_t addr = abase + row * 128 + (uint32_t)((kc ^ (row & 7)) << 4);
                ldsm4(afr[mi][0], afr[mi][1], afr[mi][2], afr[mi][3], addr);
            }
#pragma unroll
            for (int nb = 0; nb < 2; nb++) {
                int row = wn * 32 + nb * 16 + ((lane >> 4) & 1) * 8 + (lane & 7);
                int kc  = s * 2 + ((lane >> 3) & 1);
                uint32_t addr = bbase + row * 128 + (uint32_t)((kc ^ (row & 7)) << 4);
                uint32_t q0, q1, q2, q3;
                ldsm4(q0, q1, q2, q3, addr);
                bfr[nb * 2][0] = q0;  bfr[nb * 2][1] = q1;
                bfr[nb * 2 + 1][0] = q2; bfr[nb * 2 + 1][1] = q3;
            }
#pragma unroll
            for (int mi = 0; mi < 4; mi++)
#pragma unroll
                for (int ni = 0; ni < 4; ni++)
                    mma16816(acc[mi][ni], afr[mi], bfr[ni]);
        }
    }

    // ---- epilogue ----
    int rbase = rowTile * 128 + wm * 64 + (lane >> 2);
    int cbase = colTile * 128 + wn * 32 + (lane & 3) * 2;
#pragma unroll
    for (int mi = 0; mi < 4; mi++) {
#pragma unroll
        for (int ni = 0; ni < 4; ni++) {
            int cc = cbase + ni * 8;
            float b0 = bias[cc], b1 = bias[cc + 1];
            float v00 = acc[mi][ni][0] + b0, v01 = acc[mi][ni][1] + b1;
            float v10 = acc[mi][ni][2] + b0, v11 = acc[mi][ni][3] + b1;
            int r0 = rbase + mi * 16, r1 = r0 + 8;
            if constexpr (RELU) {
                v00 = fmaxf(v00, 0.f); v01 = fmaxf(v01, 0.f);
                v10 = fmaxf(v10, 0.f); v11 = fmaxf(v11, 0.f);
                if (r0 < M) *(__half2*)(OutH + (size_t)r0 * D + cc) = __floats2half2_rn(v00, v01);
                if (r1 < M) *(__half2*)(OutH + (size_t)r1 * D + cc) = __floats2half2_rn(v10, v11);
            } else {
                if (r0 < M) *(float2*)(OutF + (size_t)r0 * D + cc) = make_float2(v00, v01);
                if (r1 < M) *(float2*)(OutF + (size_t)r1 * D + cc) = make_float2(v10, v11);
            }
        }
    }
}

// ======================= combine =======================
__global__ void __launch_bounds__(256) combine_kernel(float* __restrict__ out)
{
    int n = blockIdx.x;
    int s0 = g_slot_of[2 * n], s1 = g_slot_of[2 * n + 1];
    float g0 = g_gate0[n], g1 = g_gate1[n];
    float4* orow = (float4*)(out + (size_t)n * D);
    float4 v = orow[threadIdx.x];
    if (s0 >= 0) {
        float4 e = ((const float4*)(g_Oexp + (size_t)s0 * D))[threadIdx.x];
        v.x += g0 * e.x; v.y += g0 * e.y; v.z += g0 * e.z; v.w += g0 * e.w;
    }
    if (s1 >= 0) {
        float4 e = ((const float4*)(g_Oexp + (size_t)s1 * D))[threadIdx.x];
        v.x += g1 * e.x; v.y += g1 * e.y; v.z += g1 * e.z; v.w += g1 * e.w;
    }
    orow[threadIdx.x] = v;
}

// ======================= launch =======================
extern "C" void kernel_launch(void* const* d_in, const int* in_sizes, int n_in,
                              void* d_out, int out_size)
{
    const float* x     = (const float*)d_in[0];
    const float* noise = (const float*)d_in[1];
    const float* Wr    = (const float*)d_in[2];
    const float* br    = (const float*)d_in[3];
    const float* Wn    = (const float*)d_in[4];
    const float* bn    = (const float*)d_in[5];
    const float* W1    = (const float*)d_in[6];
    const float* b1    = (const float*)d_in[7];
    const float* W2    = (const float*)d_in[8];
    const float* b2    = (const float*)d_in[9];
    const float* Ws1   = (const float*)d_in[10];
    const float* bs1   = (const float*)d_in[11];
    const float* Ws2   = (const float*)d_in[12];
    const float* bs2   = (const float*)d_in[13];
    float* out = (float*)d_out;

    cudaFuncSetAttribute(moe_gemm<1>, cudaFuncAttributeMaxDynamicSharedMemorySize, GEMM_SMEM);
    cudaFuncSetAttribute(moe_gemm<2>, cudaFuncAttributeMaxDynamicSharedMemorySize, GEMM_SMEM);

    router_kernel<<<NTOK, 256>>>(x, noise, Wr, br, Wn, bn);
    init_slots<<<(NSLOTS + 255) / 256, 256>>>();
    scan_kernel<<<1, 1024>>>(out, out_size - 1);

    split_x_kernel<<<(NTOK * D) / 256, 256>>>(x);
    dim3 wsb(32, 8);
    wsplit_kernel<0><<<dim3(32, 32, 1),   wsb>>>(Ws1);
    wsplit_kernel<1><<<dim3(32, 32, 1),   wsb>>>(Ws2);
    wsplit_kernel<2><<<dim3(32, 32, EXP), wsb>>>(W1);
    wsplit_kernel<3><<<dim3(32, 32, EXP), wsb>>>(W2);

    // FFN1 (experts + shared, flattened grid), then FFN2
    moe_gemm<1><<<dim3(D / 128, NYT), 256, GEMM_SMEM>>>(b1, bs1, nullptr);
    moe_gemm<2><<<dim3(D / 128, NYT), 256, GEMM_SMEM>>>(b2, bs2, out);

    combine_kernel<<<NTOK, 256>>>(out);
}

// round 11
// speedup vs baseline: 2.6944x; 1.0600x over previous
#include <cuda_runtime.h>
#include <cuda_fp16.h>
#include <math.h>
#include <stdint.h>

#define D 1024
#define EXP 7
#define NTOK 8192
#define CAP 2574            // int(8192*2/7*1.1)
#define NSLOTS (EXP*CAP)    // 18018

// ======================= device scratch (no runtime allocation) =======================
// Referenced ONLY from device code (host-side symbol addresses of __device__ vars are invalid).
__device__ alignas(16) __half g_x16[NTOK * D];
__device__ alignas(16) __half g_Hs[NTOK * D];
__device__ alignas(16) __half g_He[NSLOTS * D];
__device__ alignas(16) __half g_W1t[EXP * D * D];
__device__ alignas(16) __half g_W2t[EXP * D * D];
__device__ alignas(16) __half g_Ws1t[D * D];
__device__ alignas(16) __half g_Ws2t[D * D];
__device__ int   g_slot_token[NSLOTS];
__device__ float g_slot_gate[NSLOTS];
__device__ int   g_top[NTOK];
__device__ float g_gate0[NTOK];
__device__ float g_gate1[NTOK];
__device__ int   g_mask[NTOK];

// ======================= helpers (base ISA only: sm_80+) =======================
__device__ __forceinline__ uint32_t smem_to_u32(const void* p) {
    uint32_t a;
    asm("{ .reg .u64 t; cvta.to.shared.u64 t, %1; cvt.u32.u64 %0, t; }" : "=r"(a) : "l"(p));
    return a;
}
__device__ __forceinline__ void ldsm4(uint32_t& r0, uint32_t& r1, uint32_t& r2, uint32_t& r3,
                                      uint32_t addr) {
    asm volatile("ldmatrix.sync.aligned.m8n8.x4.shared.b16 {%0,%1,%2,%3}, [%4];"
                 : "=r"(r0), "=r"(r1), "=r"(r2), "=r"(r3) : "r"(addr));
}
__device__ __forceinline__ void mma16816(float* d, const uint32_t* a, const uint32_t* b) {
    asm volatile(
        "mma.sync.aligned.m16n8k16.row.col.f32.f16.f16.f32 "
        "{%0,%1,%2,%3}, {%4,%5,%6,%7}, {%8,%9}, {%0,%1,%2,%3};"
        : "+f"(d[0]), "+f"(d[1]), "+f"(d[2]), "+f"(d[3])
        : "r"(a[0]), "r"(a[1]), "r"(a[2]), "r"(a[3]), "r"(b[0]), "r"(b[1]));
}
__device__ __forceinline__ void cp_async16(uint32_t dst, const void* src, int src_size) {
    asm volatile("cp.async.cg.shared.global [%0], [%1], 16, %2;"
                 :: "r"(dst), "l"(src), "r"(src_size) : "memory");
}
#define CP_COMMIT() asm volatile("cp.async.commit_group;" ::: "memory")
#define CP_WAIT1()  asm volatile("cp.async.wait_group 1;" ::: "memory")

// ======================= router (+ zero out row + x->fp16 convert) =======================
__global__ void __launch_bounds__(256) router_kernel(
    const float* __restrict__ x, const float* __restrict__ noise,
    const float* __restrict__ Wr, const float* __restrict__ br,
    const float* __restrict__ Wn, const float* __restrict__ bn,
    float* __restrict__ out)
{
    int n = blockIdx.x;
    const float* xr = x + (size_t)n * D;
    // zero this token's output row (FFN2 accumulates atomically into it)
    ((float4*)(out + (size_t)n * D))[threadIdx.x] = make_float4(0.f, 0.f, 0.f, 0.f);

    float aR[EXP], aN[EXP];
#pragma unroll
    for (int e = 0; e < EXP; e++) { aR[e] = 0.f; aN[e] = 0.f; }
    for (int d = threadIdx.x; d < D; d += 256) {
        float xv = xr[d];
        g_x16[(size_t)n * D + d] = __float2half(xv);
        const float* wr = Wr + d * EXP;
        const float* wn = Wn + d * EXP;
#pragma unroll
        for (int e = 0; e < EXP; e++) {
            aR[e] = fmaf(xv, wr[e], aR[e]);
            aN[e] = fmaf(xv, wn[e], aN[e]);
        }
    }
    __shared__ float wred[8][14];
    int lane = threadIdx.x & 31, warp = threadIdx.x >> 5;
#pragma unroll
    for (int i = 0; i < 14; i++) {
        float v = (i < EXP) ? aR[i] : aN[i - EXP];
#pragma unroll
        for (int o = 16; o > 0; o >>= 1) v += __shfl_down_sync(0xffffffffu, v, o);
        if (lane == 0) wred[warp][i] = v;
    }
    __syncthreads();
    if (threadIdx.x == 0) {
        float logit[EXP];
#pragma unroll
        for (int e = 0; e < EXP; e++) {
            float sR = 0.f, sN = 0.f;
#pragma unroll
            for (int w = 0; w < 8; w++) { sR += wred[w][e]; sN += wred[w][e + EXP]; }
            float z  = sN + bn[e];
            float sp = (z > 20.f) ? z : log1pf(expf(z));
            logit[e] = sR + br[e] + noise[(size_t)n * EXP + e] * sp;
        }
        int e0 = 0; float v0 = logit[0];
#pragma unroll
        for (int e = 1; e < EXP; e++) if (logit[e] > v0) { v0 = logit[e]; e0 = e; }
        int e1 = -1; float v1 = -INFINITY;
#pragma unroll
        for (int e = 0; e < EXP; e++) if (e != e0 && logit[e] > v1) { v1 = logit[e]; e1 = e; }
        float ex = expf(v1 - v0);
        g_top[n]   = e0 | (e1 << 4);
        g_gate0[n] = 1.f / (1.f + ex);
        g_gate1[n] = ex / (1.f + ex);
        g_mask[n]  = (1 << e0) | (1 << e1);
    }
}

// ======================= slot init =======================
__global__ void init_slots()
{
    int i = blockIdx.x * 256 + threadIdx.x;
    if (i < NSLOTS) g_slot_token[i] = 1 << 30;
}

// ======================= ordered capacity scan (single block, batched ballots) ==========
__global__ void __launch_bounds__(1024) scan_kernel(float* __restrict__ dout, int lbl_idx)
{
    __shared__ int   base[EXP];
    __shared__ float probsum[EXP];
    __shared__ int   cnt[EXP];
    __shared__ int   wcnt[EXP][32];
    __shared__ int   woff[EXP][32];
    __shared__ int   total[EXP];
    int tid = threadIdx.x, lane = tid & 31, warp = tid >> 5;
    if (tid < EXP) { base[tid] = 0; probsum[tid] = 0.f; cnt[tid] = 0; }
    __syncthreads();

    for (int tile = 0; tile < NTOK / 1024; tile++) {
        int n  = tile * 1024 + tid;
        int mk = g_mask[n];
        int tp = g_top[n];
        int e0 = tp & 15, e1 = (tp >> 4) & 15;
        float g0 = g_gate0[n], g1 = g_gate1[n];
        atomicAdd(&probsum[e0], g0);
        atomicAdd(&probsum[e1], g1);
        atomicAdd(&cnt[e0], 1);
        atomicAdd(&cnt[e1], 1);
        unsigned bal[EXP];
#pragma unroll
        for (int e = 0; e < EXP; e++) {
            bal[e] = __ballot_sync(0xffffffffu, (mk >> e) & 1);
            if (lane == 0) wcnt[e][warp] = __popc(bal[e]);
        }
        __syncthreads();
        if (warp == 0) {
#pragma unroll
            for (int e = 0; e < EXP; e++) {
                int v = wcnt[e][lane];
                int inc = v;
#pragma unroll
                for (int o = 1; o < 32; o <<= 1) {
                    int t = __shfl_up_sync(0xffffffffu, inc, o);
                    if (lane >= o) inc += t;
                }
                woff[e][lane] = inc - v;
                if (lane == 31) total[e] = inc;
            }
        }
        __syncthreads();
        unsigned lm = (1u << lane) - 1u;
#pragma unroll
        for (int e = 0; e < EXP; e++) {
            if ((mk >> e) & 1) {
                int pos = base[e] + woff[e][warp] + __popc(bal[e] & lm);
                if (pos < CAP) {
                    int slot = e * CAP + pos;
                    g_slot_token[slot] = n;
                    g_slot_gate[slot]  = (e == e0) ? g0 : g1;
                }
            }
        }
        __syncthreads();
        if (tid < EXP) base[tid] += total[tid];
        __syncthreads();
    }
    if (tid == 0) {
        float s = 0.f;
#pragma unroll
        for (int e = 0; e < EXP; e++)
            s += (probsum[e] / (float)NTOK) * ((float)cnt[e] / (float)NTOK);
        dout[lbl_idx] = (float)EXP * s;
    }
}

// ======================= weight transpose+convert (single launch, z=16 mats) ============
// W[k][n] fp32 -> Wt[n][k] fp16.  z: 0..6 -> W1[z], 7..13 -> W2[z-7], 14 -> Ws1, 15 -> Ws2
__global__ void __launch_bounds__(256) wprep_kernel(
    const float* __restrict__ W1, const float* __restrict__ W2,
    const float* __restrict__ Ws1, const float* __restrict__ Ws2)
{
    int zz = blockIdx.z;
    const float* Wsrc; __half* dst;
    if (zz < EXP)            { Wsrc = W1 + (size_t)zz * D * D;        dst = g_W1t + (size_t)zz * D * D; }
    else if (zz < 2 * EXP)   { Wsrc = W2 + (size_t)(zz - EXP) * D * D; dst = g_W2t + (size_t)(zz - EXP) * D * D; }
    else if (zz == 2 * EXP)  { Wsrc = Ws1; dst = g_Ws1t; }
    else                     { Wsrc = Ws2; dst = g_Ws2t; }
    __shared__ float t[32][33];
    int n0 = blockIdx.x * 32, k0 = blockIdx.y * 32;
    int tx = threadIdx.x, ty = threadIdx.y;
#pragma unroll
    for (int r = 0; r < 4; r++) {
        int k = k0 + ty + r * 8;
        t[ty + r * 8][tx] = Wsrc[(size_t)k * D + n0 + tx];
    }
    __syncthreads();
#pragma unroll
    for (int r = 0; r < 4; r++) {
        int n = n0 + ty + r * 8;
        int k = k0 + tx;
        dst[(size_t)n * D + k] = __float2half(t[tx][ty + r * 8]);
    }
}

// ======================= HMMA fp16 GEMM (merged shared+expert, fused scatter) ===========
// Block 128x128, K = 1024 in 16 chunks of 64. fp32 accumulate.
// 3-stage cp.async pipeline, ONE barrier per chunk. 256 threads, 2 CTAs/SM.
// Flattened grid: y in [0,147) -> expert z=y/21 row=y%21 ; y in [147,211) -> shared row=y-147.
// PHASE 1: A=x16(gathered for experts) -> relu -> He[z]/Hs (fp16)
// PHASE 2: shared: atomicAdd out[row]; expert: atomicAdd out[token] += gate*(v) (scatter)
#define NCHUNK 16
#define NSTAGE 3
#define STAGE_BYTES 32768            // A 16KB + B 16KB
#define GEMM_SMEM (NSTAGE * STAGE_BYTES + 2048)
#define ROWTILES_EXP ((CAP + 127) / 128)   // 21
#define ROWTILES_SH  (NTOK / 128)          // 64
#define NYT (EXP * ROWTILES_EXP + ROWTILES_SH)   // 211

template <int PHASE>
__global__ void __launch_bounds__(256, 2) moe_gemm(
    const float* __restrict__ bias_exp, const float* __restrict__ bias_sh,
    float* __restrict__ OutF)
{
    constexpr bool RELU = (PHASE == 1);
    int colTile = blockIdx.x;
    int y = blockIdx.y;
    bool shared_e = (y >= EXP * ROWTILES_EXP);
    int z = shared_e ? EXP : (y / ROWTILES_EXP);
    int rowTile = shared_e ? (y - EXP * ROWTILES_EXP) : (y % ROWTILES_EXP);
    int M = shared_e ? NTOK : CAP;

    extern __shared__ char smem[];
    uint32_t smem_base = smem_to_u32(smem);
    int tid = threadIdx.x, wid = tid >> 5, lane = tid & 31;
    int wm = wid & 1, wn = wid >> 1;          // 2 x 4 warp grid; warp tile 64x32

    const __half *A, *B;
    const float* bias;
    __half *OutH = nullptr;
    if constexpr (PHASE == 1) {
        if (shared_e) {
            A = g_x16; B = g_Ws1t; bias = bias_sh; OutH = g_Hs;
        } else {
            A = g_x16; B = g_W1t + (size_t)z * D * D;
            bias = bias_exp + (size_t)z * D;
            OutH = g_He + (size_t)z * CAP * D;
        }
    } else {
        if (shared_e) {
            A = g_Hs; B = g_Ws2t; bias = bias_sh;
        } else {
            A = g_He + (size_t)z * CAP * D;
            B = g_W2t + (size_t)z * D * D;
            bias = bias_exp + (size_t)z * D;
        }
    }

    int*   s_rowsrc = (int*)(smem + NSTAGE * STAGE_BYTES);
    int*   s_tok    = (int*)(smem + NSTAGE * STAGE_BYTES + 512);
    float* s_gate   = (float*)(smem + NSTAGE * STAGE_BYTES + 1024);
    if (tid < 128) {
        int gr = rowTile * 128 + tid;
        int src;
        if (PHASE == 1 && !shared_e) {
            // gather: A row = token id for this slot
            int t = (gr < M) ? g_slot_token[z * CAP + gr] : (1 << 30);
            src = ((unsigned)t < (unsigned)NTOK) ? t : -1;
        } else {
            src = (gr < M) ? gr : -1;
        }
        s_rowsrc[tid] = src;
        if (PHASE == 2 && !shared_e) {
            int t = (gr < M) ? g_slot_token[z * CAP + gr] : (1 << 30);
            s_tok[tid]  = ((unsigned)t < (unsigned)NTOK) ? t : -1;
            s_gate[tid] = (gr < M) ? g_slot_gate[z * CAP + gr] : 0.f;
        }
    }
    __syncthreads();

    // ---- stage loader: chunk c into stage buffer buf ----
    auto load_stage = [&](int c, int buf) {
        int kb = c * 64;
        uint32_t abase = smem_base + buf * STAGE_BYTES;
        uint32_t bbase = abase + 16384;
#pragma unroll
        for (int i = 0; i < 4; i++) {
            int chunk = i * 256 + tid;
            int row = chunk >> 3, c0 = chunk & 7;
            uint32_t swc = (uint32_t)(c0 ^ (row & 7));
            int src = s_rowsrc[row];
            const void* ap = A + (size_t)(src < 0 ? 0 : src) * D + kb + c0 * 8;
            cp_async16(abase + row * 128 + swc * 16, ap, src < 0 ? 0 : 16);
            int n = colTile * 128 + row;
            cp_async16(bbase + row * 128 + swc * 16,
                       B + (size_t)n * D + kb + c0 * 8, 16);
        }
    };

    float acc[4][4][4];
#pragma unroll
    for (int mi = 0; mi < 4; mi++)
#pragma unroll
        for (int ni = 0; ni < 4; ni++)
#pragma unroll
            for (int q = 0; q < 4; q++) acc[mi][ni][q] = 0.f;

    load_stage(0, 0); CP_COMMIT();
    load_stage(1, 1); CP_COMMIT();

    for (int c = 0; c < NCHUNK; c++) {
        int buf = c % NSTAGE;
        CP_WAIT1();            // chunk c complete (chunk c+1 may be in flight)
        __syncthreads();       // data visible; prior reads of buffer (c+2)%3 done
        if (c + 2 < NCHUNK) load_stage(c + 2, (c + 2) % NSTAGE);
        CP_COMMIT();
        uint32_t abase = smem_base + buf * STAGE_BYTES;
        uint32_t bbase = abase + 16384;
#pragma unroll
        for (int s = 0; s < 4; s++) {
            uint32_t afr[4][4], bfr[4][2];
#pragma unroll
            for (int mi = 0; mi < 4; mi++) {
                int row = wm * 64 + mi * 16 + (lane & 15);
                int kc  = s * 2 + (lane >> 4);
                uint32_t addr = abase + row * 128 + (uint32_t)((kc ^ (row & 7)) << 4);
                ldsm4(afr[mi][0], afr[mi][1], afr[mi][2], afr[mi][3], addr);
            }
#pragma unroll
            for (int nb = 0; nb < 2; nb++) {
                int row = wn * 32 + nb * 16 + ((lane >> 4) & 1) * 8 + (lane & 7);
                int kc  = s * 2 + ((lane >> 3) & 1);
                uint32_t addr = bbase + row * 128 + (uint32_t)((kc ^ (row & 7)) << 4);
                uint32_t q0, q1, q2, q3;
                ldsm4(q0, q1, q2, q3, addr);
                bfr[nb * 2][0] = q0;  bfr[nb * 2][1] = q1;
                bfr[nb * 2 + 1][0] = q2; bfr[nb * 2 + 1][1] = q3;
            }
#pragma unroll
            for (int mi = 0; mi < 4; mi++)
#pragma unroll
                for (int ni = 0; ni < 4; ni++)
                    mma16816(acc[mi][ni], afr[mi], bfr[ni]);
        }
    }

    // ---- epilogue ----
    int rit0 = wm * 64 + (lane >> 2);          // row within tile for mi=0 (and +8 sibling)
    int cbase = colTile * 128 + wn * 32 + (lane & 3) * 2;
#pragma unroll
    for (int mi = 0; mi < 4; mi++) {
        int r0it = rit0 + mi * 16, r1it = r0it + 8;
        int r0 = rowTile * 128 + r0it, r1 = rowTile * 128 + r1it;
#pragma unroll
        for (int ni = 0; ni < 4; ni++) {
            int cc = cbase + ni * 8;
            float b0 = bias[cc], b1 = bias[cc + 1];
            float v00 = acc[mi][ni][0] + b0, v01 = acc[mi][ni][1] + b1;
            float v10 = acc[mi][ni][2] + b0, v11 = acc[mi][ni][3] + b1;
            if constexpr (RELU) {
                v00 = fmaxf(v00, 0.f); v01 = fmaxf(v01, 0.f);
                v10 = fmaxf(v10, 0.f); v11 = fmaxf(v11, 0.f);
                if (r0 < M) *(__half2*)(OutH + (size_t)r0 * D + cc) = __floats2half2_rn(v00, v01);
                if (r1 < M) *(__half2*)(OutH + (size_t)r1 * D + cc) = __floats2half2_rn(v10, v11);
            } else {
                if (shared_e) {
                    if (r0 < M) {
                        atomicAdd(OutF + (size_t)r0 * D + cc,     v00);
                        atomicAdd(OutF + (size_t)r0 * D + cc + 1, v01);
                    }
                    if (r1 < M) {
                        atomicAdd(OutF + (size_t)r1 * D + cc,     v10);
                        atomicAdd(OutF + (size_t)r1 * D + cc + 1, v11);
                    }
                } else {
                    int t0 = s_tok[r0it], t1 = s_tok[r1it];
                    float ga = s_gate[r0it], gb = s_gate[r1it];
                    if (t0 >= 0) {
                        atomicAdd(OutF + (size_t)t0 * D + cc,     ga * v00);
                        atomicAdd(OutF + (size_t)t0 * D + cc + 1, ga * v01);
                    }
                    if (t1 >= 0) {
                        atomicAdd(OutF + (size_t)t1 * D + cc,     gb * v10);
                        atomicAdd(OutF + (size_t)t1 * D + cc + 1, gb * v11);
                    }
                }
            }
        }
    }
}

// ======================= launch =======================
extern "C" void kernel_launch(void* const* d_in, const int* in_sizes, int n_in,
                              void* d_out, int out_size)
{
    const float* x     = (const float*)d_in[0];
    const float* noise = (const float*)d_in[1];
    const float* Wr    = (const float*)d_in[2];
    const float* br    = (const float*)d_in[3];
    const float* Wn    = (const float*)d_in[4];
    const float* bn    = (const float*)d_in[5];
    const float* W1    = (const float*)d_in[6];
    const float* b1    = (const float*)d_in[7];
    const float* W2    = (const float*)d_in[8];
    const float* b2    = (const float*)d_in[9];
    const float* Ws1   = (const float*)d_in[10];
    const float* bs1   = (const float*)d_in[11];
    const float* Ws2   = (const float*)d_in[12];
    const float* bs2   = (const float*)d_in[13];
    float* out = (float*)d_out;

    cudaFuncSetAttribute(moe_gemm<1>, cudaFuncAttributeMaxDynamicSharedMemorySize, GEMM_SMEM);
    cudaFuncSetAttribute(moe_gemm<2>, cudaFuncAttributeMaxDynamicSharedMemorySize, GEMM_SMEM);

    router_kernel<<<NTOK, 256>>>(x, noise, Wr, br, Wn, bn, out);
    init_slots<<<(NSLOTS + 255) / 256, 256>>>();
    scan_kernel<<<1, 1024>>>(out, out_size - 1);
    wprep_kernel<<<dim3(32, 32, 2 * EXP + 2), dim3(32, 8)>>>(W1, W2, Ws1, Ws2);

    // FFN1 (experts + shared, flattened grid), then FFN2 (fused gate+scatter into out)
    moe_gemm<1><<<dim3(D / 128, NYT), 256, GEMM_SMEM>>>(b1, bs1, nullptr);
    moe_gemm<2><<<dim3(D / 128, NYT), 256, GEMM_SMEM>>>(b2, bs2, out);
}

// round 12
// speedup vs baseline: 2.7452x; 1.0189x over previous
#include <cuda_runtime.h>
#include <cuda_fp16.h>
#include <math.h>
#include <stdint.h>

#define D 1024
#define EXP 7
#define NTOK 8192
#define CAP 2574            // int(8192*2/7*1.1)
#define NSLOTS (EXP*CAP)    // 18018

// ======================= device scratch (no runtime allocation) =======================
// Referenced ONLY from device code (host-side symbol addresses of __device__ vars are invalid).
__device__ alignas(16) __half g_x16[NTOK * D];
__device__ alignas(16) __half g_Hs[NTOK * D];
__device__ alignas(16) __half g_He[NSLOTS * D];
__device__ alignas(16) __half g_W1t[EXP * D * D];
__device__ alignas(16) __half g_W2t[EXP * D * D];
__device__ alignas(16) __half g_Ws1t[D * D];
__device__ alignas(16) __half g_Ws2t[D * D];
__device__ int   g_slot_token[NSLOTS];
__device__ float g_slot_gate[NSLOTS];
__device__ int   g_top[NTOK];
__device__ float g_gate0[NTOK];
__device__ float g_gate1[NTOK];
__device__ int   g_mask[NTOK];

// ======================= helpers (base ISA only: sm_80+) =======================
__device__ __forceinline__ uint32_t smem_to_u32(const void* p) {
    uint32_t a;
    asm("{ .reg .u64 t; cvta.to.shared.u64 t, %1; cvt.u32.u64 %0, t; }" : "=r"(a) : "l"(p));
    return a;
}
__device__ __forceinline__ void ldsm4(uint32_t& r0, uint32_t& r1, uint32_t& r2, uint32_t& r3,
                                      uint32_t addr) {
    asm volatile("ldmatrix.sync.aligned.m8n8.x4.shared.b16 {%0,%1,%2,%3}, [%4];"
                 : "=r"(r0), "=r"(r1), "=r"(r2), "=r"(r3) : "r"(addr));
}
__device__ __forceinline__ void mma16816(float* d, const uint32_t* a, const uint32_t* b) {
    asm volatile(
        "mma.sync.aligned.m16n8k16.row.col.f32.f16.f16.f32 "
        "{%0,%1,%2,%3}, {%4,%5,%6,%7}, {%8,%9}, {%0,%1,%2,%3};"
        : "+f"(d[0]), "+f"(d[1]), "+f"(d[2]), "+f"(d[3])
        : "r"(a[0]), "r"(a[1]), "r"(a[2]), "r"(a[3]), "r"(b[0]), "r"(b[1]));
}
__device__ __forceinline__ void cp_async16(uint32_t dst, const void* src, int src_size) {
    asm volatile("cp.async.cg.shared.global [%0], [%1], 16, %2;"
                 :: "r"(dst), "l"(src), "r"(src_size) : "memory");
}
#define CP_COMMIT() asm volatile("cp.async.commit_group;" ::: "memory")
#define CP_WAIT1()  asm volatile("cp.async.wait_group 1;" ::: "memory")

// ======================= router (+ zero out row + x->fp16 convert) =======================
__global__ void __launch_bounds__(256) router_kernel(
    const float* __restrict__ x, const float* __restrict__ noise,
    const float* __restrict__ Wr, const float* __restrict__ br,
    const float* __restrict__ Wn, const float* __restrict__ bn,
    float* __restrict__ out)
{
    int n = blockIdx.x;
    const float* xr = x + (size_t)n * D;
    // zero this token's output row (FFN2 accumulates atomically into it)
    ((float4*)(out + (size_t)n * D))[threadIdx.x] = make_float4(0.f, 0.f, 0.f, 0.f);

    float aR[EXP], aN[EXP];
#pragma unroll
    for (int e = 0; e < EXP; e++) { aR[e] = 0.f; aN[e] = 0.f; }
    for (int d = threadIdx.x; d < D; d += 256) {
        float xv = xr[d];
        g_x16[(size_t)n * D + d] = __float2half(xv);
        const float* wr = Wr + d * EXP;
        const float* wn = Wn + d * EXP;
#pragma unroll
        for (int e = 0; e < EXP; e++) {
            aR[e] = fmaf(xv, wr[e], aR[e]);
            aN[e] = fmaf(xv, wn[e], aN[e]);
        }
    }
    __shared__ float wred[8][14];
    int lane = threadIdx.x & 31, warp = threadIdx.x >> 5;
#pragma unroll
    for (int i = 0; i < 14; i++) {
        float v = (i < EXP) ? aR[i] : aN[i - EXP];
#pragma unroll
        for (int o = 16; o > 0; o >>= 1) v += __shfl_down_sync(0xffffffffu, v, o);
        if (lane == 0) wred[warp][i] = v;
    }
    __syncthreads();
    if (threadIdx.x == 0) {
        float logit[EXP];
#pragma unroll
        for (int e = 0; e < EXP; e++) {
            float sR = 0.f, sN = 0.f;
#pragma unroll
            for (int w = 0; w < 8; w++) { sR += wred[w][e]; sN += wred[w][e + EXP]; }
            float z  = sN + bn[e];
            float sp = (z > 20.f) ? z : log1pf(expf(z));
            logit[e] = sR + br[e] + noise[(size_t)n * EXP + e] * sp;
        }
        int e0 = 0; float v0 = logit[0];
#pragma unroll
        for (int e = 1; e < EXP; e++) if (logit[e] > v0) { v0 = logit[e]; e0 = e; }
        int e1 = -1; float v1 = -INFINITY;
#pragma unroll
        for (int e = 0; e < EXP; e++) if (e != e0 && logit[e] > v1) { v1 = logit[e]; e1 = e; }
        float ex = expf(v1 - v0);
        g_top[n]   = e0 | (e1 << 4);
        g_gate0[n] = 1.f / (1.f + ex);
        g_gate1[n] = ex / (1.f + ex);
        g_mask[n]  = (1 << e0) | (1 << e1);
    }
}

// ======================= weight transpose+convert + slot init (single launch) ===========
// z: 0..6 -> W1[z], 7..13 -> W2[z-7], 14 -> Ws1, 15 -> Ws2, 16 -> init g_slot_token
__global__ void __launch_bounds__(256) wprep_kernel(
    const float* __restrict__ W1, const float* __restrict__ W2,
    const float* __restrict__ Ws1, const float* __restrict__ Ws2)
{
    int zz = blockIdx.z;
    int tid = threadIdx.y * 32 + threadIdx.x;
    if (zz == 2 * EXP + 2) {
        int idx = (blockIdx.y * 32 + blockIdx.x) * 256 + tid;
        if (idx < NSLOTS) g_slot_token[idx] = 1 << 30;
        return;
    }
    const float* Wsrc; __half* dst;
    if (zz < EXP)            { Wsrc = W1 + (size_t)zz * D * D;         dst = g_W1t + (size_t)zz * D * D; }
    else if (zz < 2 * EXP)   { Wsrc = W2 + (size_t)(zz - EXP) * D * D; dst = g_W2t + (size_t)(zz - EXP) * D * D; }
    else if (zz == 2 * EXP)  { Wsrc = Ws1; dst = g_Ws1t; }
    else                     { Wsrc = Ws2; dst = g_Ws2t; }
    __shared__ float t[32][33];
    int n0 = blockIdx.x * 32, k0 = blockIdx.y * 32;
    int tx = threadIdx.x, ty = threadIdx.y;
#pragma unroll
    for (int r = 0; r < 4; r++) {
        int k = k0 + ty + r * 8;
        t[ty + r * 8][tx] = Wsrc[(size_t)k * D + n0 + tx];
    }
    __syncthreads();
#pragma unroll
    for (int r = 0; r < 4; r++) {
        int n = n0 + ty + r * 8;
        int k = k0 + tx;
        dst[(size_t)n * D + k] = __float2half(t[tx][ty + r * 8]);
    }
}

// ======================= ordered capacity scan (single block, batched ballots) ==========
__global__ void __launch_bounds__(1024) scan_kernel(float* __restrict__ dout, int lbl_idx)
{
    __shared__ int   base[EXP];
    __shared__ float probsum[EXP];
    __shared__ int   cnt[EXP];
    __shared__ int   wcnt[EXP][32];
    __shared__ int   woff[EXP][32];
    __shared__ int   total[EXP];
    int tid = threadIdx.x, lane = tid & 31, warp = tid >> 5;
    if (tid < EXP) { base[tid] = 0; probsum[tid] = 0.f; cnt[tid] = 0; }
    __syncthreads();

    for (int tile = 0; tile < NTOK / 1024; tile++) {
        int n  = tile * 1024 + tid;
        int mk = g_mask[n];
        int tp = g_top[n];
        int e0 = tp & 15, e1 = (tp >> 4) & 15;
        float g0 = g_gate0[n], g1 = g_gate1[n];
        atomicAdd(&probsum[e0], g0);
        atomicAdd(&probsum[e1], g1);
        atomicAdd(&cnt[e0], 1);
        atomicAdd(&cnt[e1], 1);
        unsigned bal[EXP];
#pragma unroll
        for (int e = 0; e < EXP; e++) {
            bal[e] = __ballot_sync(0xffffffffu, (mk >> e) & 1);
            if (lane == 0) wcnt[e][warp] = __popc(bal[e]);
        }
        __syncthreads();
        if (warp == 0) {
#pragma unroll
            for (int e = 0; e < EXP; e++) {
                int v = wcnt[e][lane];
                int inc = v;
#pragma unroll
                for (int o = 1; o < 32; o <<= 1) {
                    int t = __shfl_up_sync(0xffffffffu, inc, o);
                    if (lane >= o) inc += t;
                }
                woff[e][lane] = inc - v;
                if (lane == 31) total[e] = inc;
            }
        }
        __syncthreads();
        unsigned lm = (1u << lane) - 1u;
#pragma unroll
        for (int e = 0; e < EXP; e++) {
            if ((mk >> e) & 1) {
                int pos = base[e] + woff[e][warp] + __popc(bal[e] & lm);
                if (pos < CAP) {
                    int slot = e * CAP + pos;
                    g_slot_token[slot] = n;
                    g_slot_gate[slot]  = (e == e0) ? g0 : g1;
                }
            }
        }
        __syncthreads();
        if (tid < EXP) base[tid] += total[tid];
        __syncthreads();
    }
    if (tid == 0) {
        float s = 0.f;
#pragma unroll
        for (int e = 0; e < EXP; e++)
            s += (probsum[e] / (float)NTOK) * ((float)cnt[e] / (float)NTOK);
        dout[lbl_idx] = (float)EXP * s;
    }
}

// ======================= HMMA fp16 GEMM (merged shared+expert, fused scatter) ===========
// Block 128x128, K = 1024 in 16 chunks of 64. fp32 accumulate.
// 3-stage cp.async pipeline, ONE barrier per chunk. A-fragment software pipeline
// (prefetch mi+1 while mma'ing mi). 256 threads, 2 CTAs/SM.
// Flattened grid: y in [0,147) -> expert z=y/21 row=y%21 ; y in [147,211) -> shared row=y-147.
// PHASE 1: A=x16(gathered for experts) -> relu -> He[z]/Hs (fp16)
// PHASE 2: shared: atomicAdd out[row]; expert: atomicAdd out[token] += gate*v (scatter)
#define NCHUNK 16
#define NSTAGE 3
#define STAGE_BYTES 32768            // A 16KB + B 16KB
#define GEMM_SMEM (NSTAGE * STAGE_BYTES + 2048)
#define ROWTILES_EXP ((CAP + 127) / 128)   // 21
#define ROWTILES_SH  (NTOK / 128)          // 64
#define NYT (EXP * ROWTILES_EXP + ROWTILES_SH)   // 211

template <int PHASE>
__global__ void __launch_bounds__(256, 2) moe_gemm(
    const float* __restrict__ bias_exp, const float* __restrict__ bias_sh,
    float* __restrict__ OutF)
{
    constexpr bool RELU = (PHASE == 1);
    int colTile = blockIdx.x;
    int y = blockIdx.y;
    bool shared_e = (y >= EXP * ROWTILES_EXP);
    int z = shared_e ? EXP : (y / ROWTILES_EXP);
    int rowTile = shared_e ? (y - EXP * ROWTILES_EXP) : (y % ROWTILES_EXP);
    int M = shared_e ? NTOK : CAP;

    extern __shared__ char smem[];
    uint32_t smem_base = smem_to_u32(smem);
    int tid = threadIdx.x, wid = tid >> 5, lane = tid & 31;
    int wm = wid & 1, wn = wid >> 1;          // 2 x 4 warp grid; warp tile 64x32

    const __half *A, *B;
    const float* bias;
    __half *OutH = nullptr;
    if constexpr (PHASE == 1) {
        if (shared_e) {
            A = g_x16; B = g_Ws1t; bias = bias_sh; OutH = g_Hs;
        } else {
            A = g_x16; B = g_W1t + (size_t)z * D * D;
            bias = bias_exp + (size_t)z * D;
            OutH = g_He + (size_t)z * CAP * D;
        }
    } else {
        if (shared_e) {
            A = g_Hs; B = g_Ws2t; bias = bias_sh;
        } else {
            A = g_He + (size_t)z * CAP * D;
            B = g_W2t + (size_t)z * D * D;
            bias = bias_exp + (size_t)z * D;
        }
    }

    int*   s_rowsrc = (int*)(smem + NSTAGE * STAGE_BYTES);
    int*   s_tok    = (int*)(smem + NSTAGE * STAGE_BYTES + 512);
    float* s_gate   = (float*)(smem + NSTAGE * STAGE_BYTES + 1024);
    if (tid < 128) {
        int gr = rowTile * 128 + tid;
        int src;
        if (PHASE == 1 && !shared_e) {
            int t = (gr < M) ? g_slot_token[z * CAP + gr] : (1 << 30);
            src = ((unsigned)t < (unsigned)NTOK) ? t : -1;
        } else {
            src = (gr < M) ? gr : -1;
        }
        s_rowsrc[tid] = src;
        if (PHASE == 2 && !shared_e) {
            int t = (gr < M) ? g_slot_token[z * CAP + gr] : (1 << 30);
            s_tok[tid]  = ((unsigned)t < (unsigned)NTOK) ? t : -1;
            s_gate[tid] = (gr < M) ? g_slot_gate[z * CAP + gr] : 0.f;
        }
    }
    __syncthreads();

    // ---- stage loader: chunk c into stage buffer buf ----
    auto load_stage = [&](int c, int buf) {
        int kb = c * 64;
        uint32_t abase = smem_base + buf * STAGE_BYTES;
        uint32_t bbase = abase + 16384;
#pragma unroll
        for (int i = 0; i < 4; i++) {
            int chunk = i * 256 + tid;
            int row = chunk >> 3, c0 = chunk & 7;
            uint32_t swc = (uint32_t)(c0 ^ (row & 7));
            int src = s_rowsrc[row];
            const void* ap = A + (size_t)(src < 0 ? 0 : src) * D + kb + c0 * 8;
            cp_async16(abase + row * 128 + swc * 16, ap, src < 0 ? 0 : 16);
            int n = colTile * 128 + row;
            cp_async16(bbase + row * 128 + swc * 16,
                       B + (size_t)n * D + kb + c0 * 8, 16);
        }
    };

    float acc[4][4][4];
#pragma unroll
    for (int mi = 0; mi < 4; mi++)
#pragma unroll
        for (int ni = 0; ni < 4; ni++)
#pragma unroll
            for (int q = 0; q < 4; q++) acc[mi][ni][q] = 0.f;

    load_stage(0, 0); CP_COMMIT();
    load_stage(1, 1); CP_COMMIT();

    for (int c = 0; c < NCHUNK; c++) {
        int buf = c % NSTAGE;
        CP_WAIT1();            // chunk c complete (chunk c+1 may be in flight)
        __syncthreads();       // data visible; prior reads of buffer (c+2)%3 done
        if (c + 2 < NCHUNK) load_stage(c + 2, (c + 2) % NSTAGE);
        CP_COMMIT();
        uint32_t abase = smem_base + buf * STAGE_BYTES;
        uint32_t bbase = abase + 16384;
#pragma unroll
        for (int s = 0; s < 4; s++) {
            uint32_t bfr[4][2];
#pragma unroll
            for (int nb = 0; nb < 2; nb++) {
                int row = wn * 32 + nb * 16 + ((lane >> 4) & 1) * 8 + (lane & 7);
                int kc  = s * 2 + ((lane >> 3) & 1);
                uint32_t addr = bbase + row * 128 + (uint32_t)((kc ^ (row & 7)) << 4);
                uint32_t q0, q1, q2, q3;
                ldsm4(q0, q1, q2, q3, addr);
                bfr[nb * 2][0] = q0;  bfr[nb * 2][1] = q1;
                bfr[nb * 2 + 1][0] = q2; bfr[nb * 2 + 1][1] = q3;
            }
            // A-fragment software pipeline: load mi=0, then prefetch mi+1 before mma(mi)
            uint32_t afr[2][4];
            {
                int row = wm * 64 + (lane & 15);
                int kc  = s * 2 + (lane >> 4);
                uint32_t addr = abase + row * 128 + (uint32_t)((kc ^ (row & 7)) << 4);
                ldsm4(afr[0][0], afr[0][1], afr[0][2], afr[0][3], addr);
            }
#pragma unroll
            for (int mi = 0; mi < 4; mi++) {
                int cur = mi & 1;
                if (mi < 3) {
                    int row = wm * 64 + (mi + 1) * 16 + (lane & 15);
                    int kc  = s * 2 + (lane >> 4);
                    uint32_t addr = abase + row * 128 + (uint32_t)((kc ^ (row & 7)) << 4);
                    ldsm4(afr[cur ^ 1][0], afr[cur ^ 1][1], afr[cur ^ 1][2], afr[cur ^ 1][3], addr);
                }
#pragma unroll
                for (int ni = 0; ni < 4; ni++)
                    mma16816(acc[mi][ni], afr[cur], bfr[ni]);
            }
        }
    }

    // ---- epilogue ----
    int rit0 = wm * 64 + (lane >> 2);
    int cbase = colTile * 128 + wn * 32 + (lane & 3) * 2;
#pragma unroll
    for (int mi = 0; mi < 4; mi++) {
        int r0it = rit0 + mi * 16, r1it = r0it + 8;
        int r0 = rowTile * 128 + r0it, r1 = rowTile * 128 + r1it;
#pragma unroll
        for (int ni = 0; ni < 4; ni++) {
            int cc = cbase + ni * 8;
            float b0 = bias[cc], b1 = bias[cc + 1];
            float v00 = acc[mi][ni][0] + b0, v01 = acc[mi][ni][1] + b1;
            float v10 = acc[mi][ni][2] + b0, v11 = acc[mi][ni][3] + b1;
            if constexpr (RELU) {
                v00 = fmaxf(v00, 0.f); v01 = fmaxf(v01, 0.f);
                v10 = fmaxf(v10, 0.f); v11 = fmaxf(v11, 0.f);
                if (r0 < M) *(__half2*)(OutH + (size_t)r0 * D + cc) = __floats2half2_rn(v00, v01);
                if (r1 < M) *(__half2*)(OutH + (size_t)r1 * D + cc) = __floats2half2_rn(v10, v11);
            } else {
                if (shared_e) {
                    if (r0 < M) {
                        atomicAdd(OutF + (size_t)r0 * D + cc,     v00);
                        atomicAdd(OutF + (size_t)r0 * D + cc + 1, v01);
                    }
                    if (r1 < M) {
                        atomicAdd(OutF + (size_t)r1 * D + cc,     v10);
                        atomicAdd(OutF + (size_t)r1 * D + cc + 1, v11);
                    }
                } else {
                    int t0 = s_tok[r0it], t1 = s_tok[r1it];
                    float ga = s_gate[r0it], gb = s_gate[r1it];
                    if (t0 >= 0) {
                        atomicAdd(OutF + (size_t)t0 * D + cc,     ga * v00);
                        atomicAdd(OutF + (size_t)t0 * D + cc + 1, ga * v01);
                    }
                    if (t1 >= 0) {
                        atomicAdd(OutF + (size_t)t1 * D + cc,     gb * v10);
                        atomicAdd(OutF + (size_t)t1 * D + cc + 1, gb * v11);
                    }
                }
            }
        }
    }
}

// ======================= launch =======================
extern "C" void kernel_launch(void* const* d_in, const int* in_sizes, int n_in,
                              void* d_out, int out_size)
{
    const float* x     = (const float*)d_in[0];
    const float* noise = (const float*)d_in[1];
    const float* Wr    = (const float*)d_in[2];
    const float* br    = (const float*)d_in[3];
    const float* Wn    = (const float*)d_in[4];
    const float* bn    = (const float*)d_in[5];
    const float* W1    = (const float*)d_in[6];
    const float* b1    = (const float*)d_in[7];
    const float* W2    = (const float*)d_in[8];
    const float* b2    = (const float*)d_in[9];
    const float* Ws1   = (const float*)d_in[10];
    const float* bs1   = (const float*)d_in[11];
    const float* Ws2   = (const float*)d_in[12];
    const float* bs2   = (const float*)d_in[13];
    float* out = (float*)d_out;

    cudaFuncSetAttribute(moe_gemm<1>, cudaFuncAttributeMaxDynamicSharedMemorySize, GEMM_SMEM);
    cudaFuncSetAttribute(moe_gemm<2>, cudaFuncAttributeMaxDynamicSharedMemorySize, GEMM_SMEM);

    router_kernel<<<NTOK, 256>>>(x, noise, Wr, br, Wn, bn, out);
    wprep_kernel<<<dim3(32, 32, 2 * EXP + 3), dim3(32, 8)>>>(W1, W2, Ws1, Ws2);  // + slot init
    scan_kernel<<<1, 1024>>>(out, out_size - 1);

    // FFN1 (experts + shared, flattened grid), then FFN2 (fused gate+scatter into out)
    moe_gemm<1><<<dim3(D / 128, NYT), 256, GEMM_SMEM>>>(b1, bs1, nullptr);
    moe_gemm<2><<<dim3(D / 128, NYT), 256, GEMM_SMEM>>>(b2, bs2, out);
}

// round 16
// speedup vs baseline: 2.7456x; 1.0001x over previous
#include <cuda_runtime.h>
#include <cuda_fp16.h>
#include <math.h>
#include <stdint.h>

#define D 1024
#define EXP 7
#define NTOK 8192
#define CAP 2574            // int(8192*2/7*1.1)
#define NSLOTS (EXP*CAP)    // 18018

// ======================= device scratch (no runtime allocation) =======================
// Referenced ONLY from device code (host-side symbol addresses of __device__ vars are invalid).
__device__ alignas(16) __half g_x16[NTOK * D];
__device__ alignas(16) __half g_Hs[NTOK * D];
__device__ alignas(16) __half g_He[NSLOTS * D];
__device__ alignas(16) __half g_W1t[EXP * D * D];
__device__ alignas(16) __half g_W2t[EXP * D * D];
__device__ alignas(16) __half g_Ws1t[D * D];
__device__ alignas(16) __half g_Ws2t[D * D];
__device__ int   g_slot_token[NSLOTS];
__device__ float g_slot_gate[NSLOTS];
__device__ int   g_top[NTOK];
__device__ float g_gate0[NTOK];
__device__ float g_gate1[NTOK];
__device__ int   g_mask[NTOK];

// ======================= helpers (base ISA only: sm_80+/sm_90) =======================
__device__ __forceinline__ uint32_t smem_to_u32(const void* p) {
    uint32_t a;
    asm("{ .reg .u64 t; cvta.to.shared.u64 t, %1; cvt.u32.u64 %0, t; }" : "=r"(a) : "l"(p));
    return a;
}
__device__ __forceinline__ void ldsm4(uint32_t& r0, uint32_t& r1, uint32_t& r2, uint32_t& r3,
                                      uint32_t addr) {
    asm volatile("ldmatrix.sync.aligned.m8n8.x4.shared.b16 {%0,%1,%2,%3}, [%4];"
                 : "=r"(r0), "=r"(r1), "=r"(r2), "=r"(r3) : "r"(addr));
}
__device__ __forceinline__ void mma16816(float* d, const uint32_t* a, const uint32_t* b) {
    asm volatile(
        "mma.sync.aligned.m16n8k16.row.col.f32.f16.f16.f32 "
        "{%0,%1,%2,%3}, {%4,%5,%6,%7}, {%8,%9}, {%0,%1,%2,%3};"
        : "+f"(d[0]), "+f"(d[1]), "+f"(d[2]), "+f"(d[3])
        : "r"(a[0]), "r"(a[1]), "r"(a[2]), "r"(a[3]), "r"(b[0]), "r"(b[1]));
}
__device__ __forceinline__ void cp_async16(uint32_t dst, const void* src, int src_size) {
    asm volatile("cp.async.cg.shared.global [%0], [%1], 16, %2;"
                 :: "r"(dst), "l"(src), "r"(src_size) : "memory");
}
__device__ __forceinline__ void red_add_v2(float* ptr, float a, float b) {
    asm volatile("red.global.add.v2.f32 [%0], {%1, %2};"
                 :: "l"(ptr), "f"(a), "f"(b) : "memory");
}
#define CP_COMMIT() asm volatile("cp.async.commit_group;" ::: "memory")
#define CP_WAIT1()  asm volatile("cp.async.wait_group 1;" ::: "memory")

// ======================= fused prep: router + weight transpose + slot init ==============
// 1-D grid: b < NTOK                -> router for token b (+ zero out row + x->fp16)
//           b in [NTOK, NTOK+16*1024) -> weight transpose tile (zz = idx>>10)
//           b in [+16*1024, +17*1024) -> g_slot_token init
__global__ void __launch_bounds__(256) prep_kernel(
    const float* __restrict__ x, const float* __restrict__ noise,
    const float* __restrict__ Wr, const float* __restrict__ br,
    const float* __restrict__ Wn, const float* __restrict__ bn,
    const float* __restrict__ W1, const float* __restrict__ W2,
    const float* __restrict__ Ws1, const float* __restrict__ Ws2,
    float* __restrict__ out)
{
    int b = blockIdx.x;
    int tid = threadIdx.x;
    if (b >= NTOK) {
        int idx = b - NTOK;
        int zz = idx >> 10;
        int rest = idx & 1023;
        if (zz == 2 * EXP + 2) {
            int i = rest * 256 + tid;
            if (i < NSLOTS) g_slot_token[i] = 1 << 30;
            return;
        }
        const float* Wsrc; __half* dst;
        if (zz < EXP)            { Wsrc = W1 + (size_t)zz * D * D;         dst = g_W1t + (size_t)zz * D * D; }
        else if (zz < 2 * EXP)   { Wsrc = W2 + (size_t)(zz - EXP) * D * D; dst = g_W2t + (size_t)(zz - EXP) * D * D; }
        else if (zz == 2 * EXP)  { Wsrc = Ws1; dst = g_Ws1t; }
        else                     { Wsrc = Ws2; dst = g_Ws2t; }
        __shared__ float t[32][33];
        int n0 = (rest & 31) * 32, k0 = (rest >> 5) * 32;
        int tx = tid & 31, ty = tid >> 5;
#pragma unroll
        for (int r = 0; r < 4; r++) {
            int k = k0 + ty + r * 8;
            t[ty + r * 8][tx] = Wsrc[(size_t)k * D + n0 + tx];
        }
        __syncthreads();
#pragma unroll
        for (int r = 0; r < 4; r++) {
            int n = n0 + ty + r * 8;
            int k = k0 + tx;
            dst[(size_t)n * D + k] = __float2half(t[tx][ty + r * 8]);
        }
        return;
    }

    // ---- router path ----
    int n = b;
    const float* xr = x + (size_t)n * D;
    ((float4*)(out + (size_t)n * D))[tid] = make_float4(0.f, 0.f, 0.f, 0.f);

    float aR[EXP], aN[EXP];
#pragma unroll
    for (int e = 0; e < EXP; e++) { aR[e] = 0.f; aN[e] = 0.f; }
    for (int d = tid; d < D; d += 256) {
        float xv = xr[d];
        g_x16[(size_t)n * D + d] = __float2half(xv);
        const float* wr = Wr + d * EXP;
        const float* wn = Wn + d * EXP;
#pragma unroll
        for (int e = 0; e < EXP; e++) {
            aR[e] = fmaf(xv, wr[e], aR[e]);
            aN[e] = fmaf(xv, wn[e], aN[e]);
        }
    }
    __shared__ float wred[8][14];
    int lane = tid & 31, warp = tid >> 5;
#pragma unroll
    for (int i = 0; i < 14; i++) {
        float v = (i < EXP) ? aR[i] : aN[i - EXP];
#pragma unroll
        for (int o = 16; o > 0; o >>= 1) v += __shfl_down_sync(0xffffffffu, v, o);
        if (lane == 0) wred[warp][i] = v;
    }
    __syncthreads();
    if (tid == 0) {
        float logit[EXP];
#pragma unroll
        for (int e = 0; e < EXP; e++) {
            float sR = 0.f, sN = 0.f;
#pragma unroll
            for (int w = 0; w < 8; w++) { sR += wred[w][e]; sN += wred[w][e + EXP]; }
            float z  = sN + bn[e];
            float sp = (z > 20.f) ? z : log1pf(expf(z));
            logit[e] = sR + br[e] + noise[(size_t)n * EXP + e] * sp;
        }
        int e0 = 0; float v0 = logit[0];
#pragma unroll
        for (int e = 1; e < EXP; e++) if (logit[e] > v0) { v0 = logit[e]; e0 = e; }
        int e1 = -1; float v1 = -INFINITY;
#pragma unroll
        for (int e = 0; e < EXP; e++) if (e != e0 && logit[e] > v1) { v1 = logit[e]; e1 = e; }
        float ex = expf(v1 - v0);
        g_top[n]   = e0 | (e1 << 4);
        g_gate0[n] = 1.f / (1.f + ex);
        g_gate1[n] = ex / (1.f + ex);
        g_mask[n]  = (1 << e0) | (1 << e1);
    }
}

// ======================= ordered capacity scan (single block, batched ballots) ==========
__global__ void __launch_bounds__(1024) scan_kernel(float* __restrict__ dout, int lbl_idx)
{
    __shared__ int   base[EXP];
    __shared__ float probsum[EXP];
    __shared__ int   cnt[EXP];
    __shared__ int   wcnt[EXP][32];
    __shared__ int   woff[EXP][32];
    __shared__ int   total[EXP];
    int tid = threadIdx.x, lane = tid & 31, warp = tid >> 5;
    if (tid < EXP) { base[tid] = 0; probsum[tid] = 0.f; cnt[tid] = 0; }
    __syncthreads();

    for (int tile = 0; tile < NTOK / 1024; tile++) {
        int n  = tile * 1024 + tid;
        int mk = g_mask[n];
        int tp = g_top[n];
        int e0 = tp & 15, e1 = (tp >> 4) & 15;
        float g0 = g_gate0[n], g1 = g_gate1[n];
        atomicAdd(&probsum[e0], g0);
        atomicAdd(&probsum[e1], g1);
        atomicAdd(&cnt[e0], 1);
        atomicAdd(&cnt[e1], 1);
        unsigned bal[EXP];
#pragma unroll
        for (int e = 0; e < EXP; e++) {
            bal[e] = __ballot_sync(0xffffffffu, (mk >> e) & 1);
            if (lane == 0) wcnt[e][warp] = __popc(bal[e]);
        }
        __syncthreads();
        if (warp == 0) {
#pragma unroll
            for (int e = 0; e < EXP; e++) {
                int v = wcnt[e][lane];
                int inc = v;
#pragma unroll
                for (int o = 1; o < 32; o <<= 1) {
                    int t = __shfl_up_sync(0xffffffffu, inc, o);
                    if (lane >= o) inc += t;
                }
                woff[e][lane] = inc - v;
                if (lane == 31) total[e] = inc;
            }
        }
        __syncthreads();
        unsigned lm = (1u << lane) - 1u;
#pragma unroll
        for (int e = 0; e < EXP; e++) {
            if ((mk >> e) & 1) {
                int pos = base[e] + woff[e][warp] + __popc(bal[e] & lm);
                if (pos < CAP) {
                    int slot = e * CAP + pos;
                    g_slot_token[slot] = n;
                    g_slot_gate[slot]  = (e == e0) ? g0 : g1;
                }
            }
        }
        __syncthreads();
        if (tid < EXP) base[tid] += total[tid];
        __syncthreads();
    }
    if (tid == 0) {
        float s = 0.f;
#pragma unroll
        for (int e = 0; e < EXP; e++)
            s += (probsum[e] / (float)NTOK) * ((float)cnt[e] / (float)NTOK);
        dout[lbl_idx] = (float)EXP * s;
    }
}

// ======================= HMMA fp16 GEMM (merged shared+expert, fused scatter) ===========
// Block 128x128, K = 1024 in 16 chunks of 64. fp32 accumulate.
// 3-stage cp.async pipeline, ONE barrier per chunk. A-fragment software pipeline.
// 256 threads, 2 CTAs/SM. Flattened grid: y<147 -> expert z=y/21 row=y%21; else shared.
// PHASE 1: A=x16(gathered for experts) -> relu -> He[z]/Hs (fp16)
// PHASE 2: shared: red.v2 out[row]; expert: red.v2 out[token] += gate*v (scatter)
#define NCHUNK 16
#define NSTAGE 3
#define STAGE_BYTES 32768            // A 16KB + B 16KB
#define GEMM_SMEM (NSTAGE * STAGE_BYTES + 2048)
#define ROWTILES_EXP ((CAP + 127) / 128)   // 21
#define ROWTILES_SH  (NTOK / 128)          // 64
#define NYT (EXP * ROWTILES_EXP + ROWTILES_SH)   // 211

template <int PHASE>
__global__ void __launch_bounds__(256, 2) moe_gemm(
    const float* __restrict__ bias_exp, const float* __restrict__ bias_sh,
    float* __restrict__ OutF)
{
    constexpr bool RELU = (PHASE == 1);
    int colTile = blockIdx.x;
    int y = blockIdx.y;
    bool shared_e = (y >= EXP * ROWTILES_EXP);
    int z = shared_e ? EXP : (y / ROWTILES_EXP);
    int rowTile = shared_e ? (y - EXP * ROWTILES_EXP) : (y % ROWTILES_EXP);
    int M = shared_e ? NTOK : CAP;

    extern __shared__ char smem[];
    uint32_t smem_base = smem_to_u32(smem);
    int tid = threadIdx.x, wid = tid >> 5, lane = tid & 31;
    int wm = wid & 1, wn = wid >> 1;          // 2 x 4 warp grid; warp tile 64x32

    const __half *A, *B;
    const float* bias;
    __half *OutH = nullptr;
    if constexpr (PHASE == 1) {
        if (shared_e) {
            A = g_x16; B = g_Ws1t; bias = bias_sh; OutH = g_Hs;
        } else {
            A = g_x16; B = g_W1t + (size_t)z * D * D;
            bias = bias_exp + (size_t)z * D;
            OutH = g_He + (size_t)z * CAP * D;
        }
    } else {
        if (shared_e) {
            A = g_Hs; B = g_Ws2t; bias = bias_sh;
        } else {
            A = g_He + (size_t)z * CAP * D;
            B = g_W2t + (size_t)z * D * D;
            bias = bias_exp + (size_t)z * D;
        }
    }

    int*   s_rowsrc = (int*)(smem + NSTAGE * STAGE_BYTES);
    int*   s_tok    = (int*)(smem + NSTAGE * STAGE_BYTES + 512);
    float* s_gate   = (float*)(smem + NSTAGE * STAGE_BYTES + 1024);
    if (tid < 128) {
        int gr = rowTile * 128 + tid;
        int src;
        if (PHASE == 1 && !shared_e) {
            int t = (gr < M) ? g_slot_token[z * CAP + gr] : (1 << 30);
            src = ((unsigned)t < (unsigned)NTOK) ? t : -1;
        } else {
            src = (gr < M) ? gr : -1;
        }
        s_rowsrc[tid] = src;
        if (PHASE == 2 && !shared_e) {
            int t = (gr < M) ? g_slot_token[z * CAP + gr] : (1 << 30);
            s_tok[tid]  = ((unsigned)t < (unsigned)NTOK) ? t : -1;
            s_gate[tid] = (gr < M) ? g_slot_gate[z * CAP + gr] : 0.f;
        }
    }
    __syncthreads();

    // ---- stage loader: chunk c into stage buffer buf ----
    auto load_stage = [&](int c, int buf) {
        int kb = c * 64;
        uint32_t abase = smem_base + buf * STAGE_BYTES;
        uint32_t bbase = abase + 16384;
#pragma unroll
        for (int i = 0; i < 4; i++) {
            int chunk = i * 256 + tid;
            int row = chunk >> 3, c0 = chunk & 7;
            uint32_t swc = (uint32_t)(c0 ^ (row & 7));
            int src = s_rowsrc[row];
            const void* ap = A + (size_t)(src < 0 ? 0 : src) * D + kb + c0 * 8;
            cp_async16(abase + row * 128 + swc * 16, ap, src < 0 ? 0 : 16);
            int n = colTile * 128 + row;
            cp_async16(bbase + row * 128 + swc * 16,
                       B + (size_t)n * D + kb + c0 * 8, 16);
        }
    };

    float acc[4][4][4];
#pragma unroll
    for (int mi = 0; mi < 4; mi++)
#pragma unroll
        for (int ni = 0; ni < 4; ni++)
#pragma unroll
            for (int q = 0; q < 4; q++) acc[mi][ni][q] = 0.f;

    load_stage(0, 0); CP_COMMIT();
    load_stage(1, 1); CP_COMMIT();

    for (int c = 0; c < NCHUNK; c++) {
        int buf = c % NSTAGE;
        CP_WAIT1();            // chunk c complete (chunk c+1 may be in flight)
        __syncthreads();       // data visible; prior reads of buffer (c+2)%3 done
        if (c + 2 < NCHUNK) load_stage(c + 2, (c + 2) % NSTAGE);
        CP_COMMIT();
        uint32_t abase = smem_base + buf * STAGE_BYTES;
        uint32_t bbase = abase + 16384;
#pragma unroll
        for (int s = 0; s < 4; s++) {
            uint32_t bfr[4][2];
#pragma unroll
            for (int nb = 0; nb < 2; nb++) {
                int row = wn * 32 + nb * 16 + ((lane >> 4) & 1) * 8 + (lane & 7);
                int kc  = s * 2 + ((lane >> 3) & 1);
                uint32_t addr = bbase + row * 128 + (uint32_t)((kc ^ (row & 7)) << 4);
                uint32_t q0, q1, q2, q3;
                ldsm4(q0, q1, q2, q3, addr);
                bfr[nb * 2][0] = q0;  bfr[nb * 2][1] = q1;
                bfr[nb * 2 + 1][0] = q2; bfr[nb * 2 + 1][1] = q3;
            }
            // A-fragment software pipeline: load mi=0, then prefetch mi+1 before mma(mi)
            uint32_t afr[2][4];
            {
                int row = wm * 64 + (lane & 15);
                int kc  = s * 2 + (lane >> 4);
                uint32_t addr = abase + row * 128 + (uint32_t)((kc ^ (row & 7)) << 4);
                ldsm4(afr[0][0], afr[0][1], afr[0][2], afr[0][3], addr);
            }
#pragma unroll
            for (int mi = 0; mi < 4; mi++) {
                int cur = mi & 1;
                if (mi < 3) {
                    int row = wm * 64 + (mi + 1) * 16 + (lane & 15);
                    int kc  = s * 2 + (lane >> 4);
                    uint32_t addr = abase + row * 128 + (uint32_t)((kc ^ (row & 7)) << 4);
                    ldsm4(afr[cur ^ 1][0], afr[cur ^ 1][1], afr[cur ^ 1][2], afr[cur ^ 1][3], addr);
                }
#pragma unroll
                for (int ni = 0; ni < 4; ni++)
                    mma16816(acc[mi][ni], afr[cur], bfr[ni]);
            }
        }
    }

    // ---- epilogue ----
    int rit0 = wm * 64 + (lane >> 2);
    int cbase = colTile * 128 + wn * 32 + (lane & 3) * 2;
#pragma unroll
    for (int mi = 0; mi < 4; mi++) {
        int r0it = rit0 + mi * 16, r1it = r0it + 8;
        int r0 = rowTile * 128 + r0it, r1 = rowTile * 128 + r1it;
#pragma unroll
        for (int ni = 0; ni < 4; ni++) {
            int cc = cbase + ni * 8;
            float b0 = bias[cc], b1 = bias[cc + 1];
            float v00 = acc[mi][ni][0] + b0, v01 = acc[mi][ni][1] + b1;
            float v10 = acc[mi][ni][2] + b0, v11 = acc[mi][ni][3] + b1;
            if constexpr (RELU) {
                v00 = fmaxf(v00, 0.f); v01 = fmaxf(v01, 0.f);
                v10 = fmaxf(v10, 0.f); v11 = fmaxf(v11, 0.f);
                if (r0 < M) *(__half2*)(OutH + (size_t)r0 * D + cc) = __floats2half2_rn(v00, v01);
                if (r1 < M) *(__half2*)(OutH + (size_t)r1 * D + cc) = __floats2half2_rn(v10, v11);
            } else {
                if (shared_e) {
                    if (r0 < M) red_add_v2(OutF + (size_t)r0 * D + cc, v00, v01);
                    if (r1 < M) red_add_v2(OutF + (size_t)r1 * D + cc, v10, v11);
                } else {
                    int t0 = s_tok[r0it], t1 = s_tok[r1it];
                    float ga = s_gate[r0it], gb = s_gate[r1it];
                    if (t0 >= 0) red_add_v2(OutF + (size_t)t0 * D + cc, ga * v00, ga * v01);
                    if (t1 >= 0) red_add_v2(OutF + (size_t)t1 * D + cc, gb * v10, gb * v11);
                }
            }
        }
    }
}

// ======================= launch =======================
extern "C" void kernel_launch(void* const* d_in, const int* in_sizes, int n_in,
                              void* d_out, int out_size)
{
    const float* x     = (const float*)d_in[0];
    const float* noise = (const float*)d_in[1];
    const float* Wr    = (const float*)d_in[2];
    const float* br    = (const float*)d_in[3];
    const float* Wn    = (const float*)d_in[4];
    const float* bn    = (const float*)d_in[5];
    const float* W1    = (const float*)d_in[6];
    const float* b1    = (const float*)d_in[7];
    const float* W2    = (const float*)d_in[8];
    const float* b2    = (const float*)d_in[9];
    const float* Ws1   = (const float*)d_in[10];
    const float* bs1   = (const float*)d_in[11];
    const float* Ws2   = (const float*)d_in[12];
    const float* bs2   = (const float*)d_in[13];
    float* out = (float*)d_out;

    cudaFuncSetAttribute(moe_gemm<1>, cudaFuncAttributeMaxDynamicSharedMemorySize, GEMM_SMEM);
    cudaFuncSetAttribute(moe_gemm<2>, cudaFuncAttributeMaxDynamicSharedMemorySize, GEMM_SMEM);

    // fused prep: router (NTOK blocks) + weight transpose (16*1024) + slot init (1024)
    prep_kernel<<<NTOK + (2 * EXP + 3) * 1024, 256>>>(
        x, noise, Wr, br, Wn, bn, W1, W2, Ws1, Ws2, out);
    scan_kernel<<<1, 1024>>>(out, out_size - 1);

    // FFN1 (experts + shared, flattened grid), then FFN2 (fused gate+scatter into out)
    moe_gemm<1><<<dim3(D / 128, NYT), 256, GEMM_SMEM>>>(b1, bs1, nullptr);
    moe_gemm<2><<<dim3(D / 128, NYT), 256, GEMM_SMEM>>>(b2, bs2, out);
}